// round 1
// baseline (speedup 1.0000x reference)
#include <cuda_runtime.h>
#include <cuda_bf16.h>
#include <math.h>

#define Bq 2
#define Tq 2048
#define Cq 1024
#define Hq 16
#define Dq 64
#define Mq (Bq*Tq)          // 4096
#define EPSq 1e-6f

// ---------------- scratch (static device globals; no allocation) -------------
__device__ float g_qpre[(size_t)Mq*Cq];
__device__ float g_kpre[(size_t)Mq*Cq];
__device__ float g_vpre[(size_t)Mq*Cq];
__device__ float g_gate[(size_t)Mq*Cq];
__device__ float g_q[(size_t)Mq*Cq];
__device__ float g_k[(size_t)Mq*Cq];
__device__ float g_v[(size_t)Mq*Cq];
__device__ float g_og[(size_t)Mq*Cq];
__device__ float g_alpha[(size_t)Mq*Hq];
__device__ float g_beta[(size_t)Mq*Hq];
__device__ float g_cos[(size_t)Tq*32];
__device__ float g_sin[(size_t)Tq*32];

// ---------------- RoPE (YaRN) cos/sin table ---------------------------------
__global__ void rope_table_kernel(float* __restrict__ ct, float* __restrict__ st) {
    int idx = blockIdx.x * blockDim.x + threadIdx.x;
    if (idx >= Tq * 32) return;
    int t = idx >> 5;
    int i = idx & 31;
    double ar = (double)i / 32.0;
    double scaled_base = 10000.0 * pow(32.0, 64.0 / 62.0);
    double inv_freq = pow(scaled_base, -ar);
    double wavelen = 2.0 * M_PI * pow(10000.0, ar);
    double mscale = (wavelen - 1.0) / 31.0;
    mscale = mscale < 0.0 ? 0.0 : (mscale > 1.0 ? 1.0 : mscale);
    double scale = 1.0 + 31.0 * mscale;
    float fr = (float)(((double)t / scale) * inv_freq);
    ct[idx] = cosf(fr);
    st[idx] = sinf(fr);
}

// ---------------- SGEMM:  C[m][n] = sum_k A[m][k] * W[n][k]  (NT form) -------
#define GBM 128
#define GBN 128
#define GBK 16

__global__ __launch_bounds__(256, 2) void sgemm_nt(
    const float* __restrict__ A, const float* __restrict__ W,
    float* __restrict__ C, int M, int N, int K)
{
    __shared__ float As[GBK][GBM + 4];
    __shared__ float Bs[GBK][GBN + 4];
    const int tid = threadIdx.x;
    const int m0 = blockIdx.x * GBM;
    const int n0 = blockIdx.y * GBN;
    const int tx = tid & 15, ty = tid >> 4;

    const int r0 = tid >> 2;            // 0..63
    const int c0 = (tid & 3) * 4;       // 0,4,8,12

    const float* Aa = A + (size_t)m0 * K;
    const float* Wa = W + (size_t)n0 * K;

    float4 pa0 = *(const float4*)(Aa + (size_t)r0 * K + c0);
    float4 pa1 = *(const float4*)(Aa + (size_t)(r0 + 64) * K + c0);
    float4 pb0 = *(const float4*)(Wa + (size_t)r0 * K + c0);
    float4 pb1 = *(const float4*)(Wa + (size_t)(r0 + 64) * K + c0);

    float acc[8][8];
#pragma unroll
    for (int i = 0; i < 8; i++)
#pragma unroll
        for (int j = 0; j < 8; j++) acc[i][j] = 0.f;

    const int nk = K / GBK;
    for (int kt = 0; kt < nk; kt++) {
        As[c0 + 0][r0] = pa0.x; As[c0 + 1][r0] = pa0.y;
        As[c0 + 2][r0] = pa0.z; As[c0 + 3][r0] = pa0.w;
        As[c0 + 0][r0 + 64] = pa1.x; As[c0 + 1][r0 + 64] = pa1.y;
        As[c0 + 2][r0 + 64] = pa1.z; As[c0 + 3][r0 + 64] = pa1.w;
        Bs[c0 + 0][r0] = pb0.x; Bs[c0 + 1][r0] = pb0.y;
        Bs[c0 + 2][r0] = pb0.z; Bs[c0 + 3][r0] = pb0.w;
        Bs[c0 + 0][r0 + 64] = pb1.x; Bs[c0 + 1][r0 + 64] = pb1.y;
        Bs[c0 + 2][r0 + 64] = pb1.z; Bs[c0 + 3][r0 + 64] = pb1.w;
        __syncthreads();

        if (kt + 1 < nk) {
            int kb = (kt + 1) * GBK + c0;
            pa0 = *(const float4*)(Aa + (size_t)r0 * K + kb);
            pa1 = *(const float4*)(Aa + (size_t)(r0 + 64) * K + kb);
            pb0 = *(const float4*)(Wa + (size_t)r0 * K + kb);
            pb1 = *(const float4*)(Wa + (size_t)(r0 + 64) * K + kb);
        }

#pragma unroll
        for (int kk = 0; kk < GBK; kk++) {
            float a[8], b[8];
            *(float4*)(a)     = *(const float4*)&As[kk][ty * 8];
            *(float4*)(a + 4) = *(const float4*)&As[kk][ty * 8 + 4];
            *(float4*)(b)     = *(const float4*)&Bs[kk][tx * 8];
            *(float4*)(b + 4) = *(const float4*)&Bs[kk][tx * 8 + 4];
#pragma unroll
            for (int i = 0; i < 8; i++)
#pragma unroll
                for (int j = 0; j < 8; j++)
                    acc[i][j] = fmaf(a[i], b[j], acc[i][j]);
        }
        __syncthreads();
    }

#pragma unroll
    for (int i = 0; i < 8; i++) {
        float* Cp = C + (size_t)(m0 + ty * 8 + i) * N + n0 + tx * 8;
        float4 v0 = make_float4(acc[i][0], acc[i][1], acc[i][2], acc[i][3]);
        float4 v1 = make_float4(acc[i][4], acc[i][5], acc[i][6], acc[i][7]);
        *(float4*)Cp = v0;
        *(float4*)(Cp + 4) = v1;
    }
}

// ---------------- beta / alpha (small GEMM N=32 + transforms) ----------------
__global__ __launch_bounds__(128) void bg_kernel(
    const float* __restrict__ x,
    const float* __restrict__ Wb, const float* __restrict__ bb,
    const float* __restrict__ Wgk, const float* __restrict__ bgk,
    const float* __restrict__ A_log, const float* __restrict__ dt_bias,
    float* __restrict__ beta, float* __restrict__ alpha)
{
    __shared__ float xs[Cq];
    const int m = blockIdx.x;
    const float4* xr = (const float4*)(x + (size_t)m * Cq);
    for (int i = threadIdx.x; i < Cq / 4; i += 128) ((float4*)xs)[i] = xr[i];
    __syncthreads();

    int warp = threadIdx.x >> 5, lane = threadIdx.x & 31;
#pragma unroll
    for (int nn = 0; nn < 8; nn++) {
        int n = warp * 8 + nn;
        const float* wr = (n < 16) ? (Wb + (size_t)n * Cq) : (Wgk + (size_t)(n - 16) * Cq);
        float acc = 0.f;
#pragma unroll 8
        for (int c = lane; c < Cq; c += 32) acc += xs[c] * __ldg(wr + c);
#pragma unroll
        for (int s = 16; s > 0; s >>= 1) acc += __shfl_xor_sync(0xffffffffu, acc, s);
        if (lane == 0) {
            if (n < 16) {
                beta[(size_t)m * Hq + n] = 1.f / (1.f + expf(-(acc + bb[n])));
            } else {
                int hh = n - 16;
                float gv = acc + bgk[hh] + dt_bias[hh];
                float sp = (gv > 20.f) ? gv : log1pf(expf(gv));
                alpha[(size_t)m * Hq + hh] = expf(-expf(A_log[hh]) * sp);
            }
        }
    }
}

// ---------------- conv(K=4)+silu, then RoPE + l2norm for q,k -----------------
__device__ __forceinline__ float conv_silu(const float* __restrict__ pre,
                                           const float* __restrict__ w,
                                           const float* __restrict__ bias,
                                           int b, int t, int c)
{
    float acc = bias[c];
#pragma unroll
    for (int i = 0; i < 4; i++) {
        int tt = t - 3 + i;
        if (tt >= 0) acc = fmaf(pre[((size_t)b * Tq + tt) * Cq + c], w[c * 4 + i], acc);
    }
    return acc / (1.f + expf(-acc));
}

__global__ __launch_bounds__(64) void conv_rope_kernel(
    const float* __restrict__ qpre, const float* __restrict__ kpre,
    const float* __restrict__ vpre,
    const float* __restrict__ cqw, const float* __restrict__ cqb,
    const float* __restrict__ ckw, const float* __restrict__ ckb,
    const float* __restrict__ cvw, const float* __restrict__ cvb,
    const float* __restrict__ ct, const float* __restrict__ st,
    float* __restrict__ qo, float* __restrict__ ko, float* __restrict__ vo)
{
    const int blk = blockIdx.x;                 // b*T*H
    const int b = blk / (Tq * Hq);
    const int rem = blk % (Tq * Hq);
    const int t = rem / Hq;
    const int h = rem % Hq;
    const int d = threadIdx.x;                  // 0..63
    const int c = h * Dq + d;
    const size_t gidx = ((size_t)b * Tq + t) * Cq + c;

    __shared__ float sq[64], sk[64], redq[2], redk[2];

    vo[gidx] = conv_silu(vpre, cvw, cvb, b, t, c);
    sq[d] = conv_silu(qpre, cqw, cqb, b, t, c);
    sk[d] = conv_silu(kpre, ckw, ckb, b, t, c);
    __syncthreads();

    // rotary: out[j] = x1*c - x2*s ; out[32+j] = x1*s + x2*c, j = d & 31
    int j = d & 31;
    int ci = (2 * j) & 31;
    float ce = ct[(size_t)t * 32 + ci];
    float se = st[(size_t)t * 32 + ci];
    float q1 = sq[2 * j], q2 = sq[2 * j + 1];
    float k1 = sk[2 * j], k2 = sk[2 * j + 1];
    float rq = (d < 32) ? (q1 * ce - q2 * se) : (q1 * se + q2 * ce);
    float rk = (d < 32) ? (k1 * ce - k2 * se) : (k1 * se + k2 * ce);

    float sq2 = rq * rq, sk2 = rk * rk;
#pragma unroll
    for (int s = 16; s > 0; s >>= 1) {
        sq2 += __shfl_xor_sync(0xffffffffu, sq2, s);
        sk2 += __shfl_xor_sync(0xffffffffu, sk2, s);
    }
    int wid = d >> 5;
    if ((d & 31) == 0) { redq[wid] = sq2; redk[wid] = sk2; }
    __syncthreads();
    float qn = redq[0] + redq[1];
    float kn = redk[0] + redk[1];
    float qinv = 1.f / fmaxf(sqrtf(qn), 1e-12f);
    float kinv = 1.f / fmaxf(sqrtf(kn), 1e-12f);
    qo[gidx] = rq * qinv;
    ko[gidx] = rk * kinv;
}

// ---------------- sequential gated-delta scan + fused epilogue ---------------
__global__ __launch_bounds__(256, 1) void scan_kernel(
    const float* __restrict__ q, const float* __restrict__ k,
    const float* __restrict__ v,
    const float* __restrict__ alpha, const float* __restrict__ beta,
    const float* __restrict__ gate, const float* __restrict__ Dp,
    const float* __restrict__ o_norm_w, float* __restrict__ og)
{
    const int bh = blockIdx.x;          // 0..31
    const int b = bh >> 4;
    const int h = bh & 15;
    const int tid = threadIdx.x;
    const int vr = tid >> 2;            // v row 0..63
    const int kg = tid & 3;             // k group (16 cols each)

    __shared__ float qs[64], ks[64], vs[64], ab[2], red[8];

    float S[16];
#pragma unroll
    for (int j = 0; j < 16; j++) S[j] = 0.f;

    const float dp = Dp[h];
    const float wnv = o_norm_w[vr];
    const size_t base = (size_t)b * Tq * Cq + h * Dq;
    const size_t abbase = (size_t)b * Tq * Hq + h;

    // prefetch registers for t=0
    float nq = 0.f, nk = 0.f, nv = 0.f, na = 0.f, nb = 0.f;
    if (tid < 64) { nq = q[base + tid]; nk = k[base + tid]; nv = v[base + tid]; }
    if (tid == 0) { na = alpha[abbase]; nb = beta[abbase]; }

    for (int t = 0; t < Tq; t++) {
        if (tid < 64) { qs[tid] = nq; ks[tid] = nk; vs[tid] = nv; }
        if (tid == 0) { ab[0] = na; ab[1] = nb; }
        __syncthreads();

        if (t + 1 < Tq) {
            size_t off = base + (size_t)(t + 1) * Cq;
            if (tid < 64) { nq = q[off + tid]; nk = k[off + tid]; nv = v[off + tid]; }
            if (tid == 0) {
                size_t abo = abbase + (size_t)(t + 1) * Hq;
                na = alpha[abo]; nb = beta[abo];
            }
        }

        float a = ab[0], bt = ab[1];
        float kr[16], qr[16];
        const float4* k4 = (const float4*)(ks + kg * 16);
        const float4* q4 = (const float4*)(qs + kg * 16);
#pragma unroll
        for (int j = 0; j < 4; j++) {
            float4 kv = k4[j], qv = q4[j];
            kr[j * 4 + 0] = kv.x; kr[j * 4 + 1] = kv.y; kr[j * 4 + 2] = kv.z; kr[j * 4 + 3] = kv.w;
            qr[j * 4 + 0] = qv.x; qr[j * 4 + 1] = qv.y; qr[j * 4 + 2] = qv.z; qr[j * 4 + 3] = qv.w;
        }
        float vv = vs[vr];

        float p = 0.f;
#pragma unroll
        for (int j = 0; j < 16; j++) p = fmaf(S[j], kr[j], p);
        p += __shfl_xor_sync(0xffffffffu, p, 1);
        p += __shfl_xor_sync(0xffffffffu, p, 2);   // Sk[vr]

        float coef = bt * vv - a * bt * p;
        float o = 0.f;
#pragma unroll
        for (int j = 0; j < 16; j++) {
            S[j] = fmaf(a, S[j], coef * kr[j]);
            o = fmaf(S[j], qr[j], o);
        }
        o += __shfl_xor_sync(0xffffffffu, o, 1);
        o += __shfl_xor_sync(0xffffffffu, o, 2);   // o[vr]

        // fused epilogue:  val = o + Dp*v ; rmsnorm over D ; silu ; * gate
        float val = o + dp * vv;
        float sqp = val * val * 0.25f;             // 4 lanes per v row
#pragma unroll
        for (int s = 16; s > 0; s >>= 1) sqp += __shfl_xor_sync(0xffffffffu, sqp, s);
        if ((tid & 31) == 0) red[tid >> 5] = sqp;
        __syncthreads();
        float ssum = red[0] + red[1] + red[2] + red[3] + red[4] + red[5] + red[6] + red[7];
        if (kg == 0) {
            float ms = ssum * (1.f / 64.f);
            float y = val * rsqrtf(ms + EPSq) * wnv;
            float sil = y / (1.f + expf(-y));
            size_t oidx = base + (size_t)t * Cq + vr;
            og[oidx] = gate[oidx] * sil;
        }
    }
}

// ---------------- launch ------------------------------------------------------
extern "C" void kernel_launch(void* const* d_in, const int* in_sizes, int n_in,
                              void* d_out, int out_size)
{
    const float* x    = (const float*)d_in[0];
    const float* Wq   = (const float*)d_in[1];
    const float* Wk   = (const float*)d_in[2];
    const float* Wv   = (const float*)d_in[3];
    const float* Wg   = (const float*)d_in[4];
    const float* Wo   = (const float*)d_in[5];
    const float* Wb   = (const float*)d_in[6];
    const float* bb   = (const float*)d_in[7];
    const float* Wgk  = (const float*)d_in[8];
    const float* bgk  = (const float*)d_in[9];
    const float* cqw  = (const float*)d_in[10];
    const float* cqb  = (const float*)d_in[11];
    const float* ckw  = (const float*)d_in[12];
    const float* ckb  = (const float*)d_in[13];
    const float* cvw  = (const float*)d_in[14];
    const float* cvb  = (const float*)d_in[15];
    const float* A_log = (const float*)d_in[16];
    const float* Dp   = (const float*)d_in[17];
    const float* dtb  = (const float*)d_in[18];
    const float* onw  = (const float*)d_in[19];
    float* out = (float*)d_out;

    float *qpre, *kpre, *vpre, *gbuf, *qn, *kn, *vn, *ogb, *al, *be, *ct, *st;
    cudaGetSymbolAddress((void**)&qpre, g_qpre);
    cudaGetSymbolAddress((void**)&kpre, g_kpre);
    cudaGetSymbolAddress((void**)&vpre, g_vpre);
    cudaGetSymbolAddress((void**)&gbuf, g_gate);
    cudaGetSymbolAddress((void**)&qn,   g_q);
    cudaGetSymbolAddress((void**)&kn,   g_k);
    cudaGetSymbolAddress((void**)&vn,   g_v);
    cudaGetSymbolAddress((void**)&ogb,  g_og);
    cudaGetSymbolAddress((void**)&al,   g_alpha);
    cudaGetSymbolAddress((void**)&be,   g_beta);
    cudaGetSymbolAddress((void**)&ct,   g_cos);
    cudaGetSymbolAddress((void**)&st,   g_sin);

    rope_table_kernel<<<(Tq * 32 + 255) / 256, 256>>>(ct, st);

    dim3 gg(Mq / GBM, Cq / GBN);
    sgemm_nt<<<gg, 256>>>(x, Wq, qpre, Mq, Cq, Cq);
    sgemm_nt<<<gg, 256>>>(x, Wk, kpre, Mq, Cq, Cq);
    sgemm_nt<<<gg, 256>>>(x, Wv, vpre, Mq, Cq, Cq);
    sgemm_nt<<<gg, 256>>>(x, Wg, gbuf, Mq, Cq, Cq);

    bg_kernel<<<Mq, 128>>>(x, Wb, bb, Wgk, bgk, A_log, dtb, be, al);

    conv_rope_kernel<<<Bq * Tq * Hq, 64>>>(qpre, kpre, vpre,
                                           cqw, cqb, ckw, ckb, cvw, cvb,
                                           ct, st, qn, kn, vn);

    scan_kernel<<<Bq * Hq, 256>>>(qn, kn, vn, al, be, gbuf, Dp, onw, ogb);

    sgemm_nt<<<gg, 256>>>(ogb, Wo, out, Mq, Cq, Cq);
}

// round 2
// speedup vs baseline: 1.0463x; 1.0463x over previous
#include <cuda_runtime.h>
#include <cuda_bf16.h>
#include <math.h>

#define Bq 2
#define Tq 2048
#define Cq 1024
#define Hq 16
#define Dq 64
#define Mq (Bq*Tq)          // 4096
#define EPSq 1e-6f

typedef unsigned long long ull;

// ---------------- packed f32x2 helpers (Blackwell FFMA2) ---------------------
__device__ __forceinline__ ull ffma2(ull a, ull b, ull c) {
    ull d; asm("fma.rn.f32x2 %0, %1, %2, %3;" : "=l"(d) : "l"(a), "l"(b), "l"(c)); return d;
}
__device__ __forceinline__ ull fmul2(ull a, ull b) {
    ull d; asm("mul.rn.f32x2 %0, %1, %2;" : "=l"(d) : "l"(a), "l"(b)); return d;
}
__device__ __forceinline__ ull fadd2(ull a, ull b) {
    ull d; asm("add.rn.f32x2 %0, %1, %2;" : "=l"(d) : "l"(a), "l"(b)); return d;
}
__device__ __forceinline__ ull pack2(float x, float y) {
    ull d; asm("mov.b64 %0, {%1, %2};" : "=l"(d) : "f"(x), "f"(y)); return d;
}
__device__ __forceinline__ float2 unpack2(ull v) {
    float x, y; asm("mov.b64 {%0, %1}, %2;" : "=f"(x), "=f"(y) : "l"(v));
    return make_float2(x, y);
}

// ---------------- scratch (static device globals; no allocation) -------------
__device__ float g_qpre[(size_t)Mq*Cq];
__device__ float g_kpre[(size_t)Mq*Cq];
__device__ float g_vpre[(size_t)Mq*Cq];
__device__ float g_gate[(size_t)Mq*Cq];
__device__ float g_q[(size_t)Mq*Cq];
__device__ float g_k[(size_t)Mq*Cq];
__device__ float g_v[(size_t)Mq*Cq];
__device__ float g_og[(size_t)Mq*Cq];
__device__ float g_alpha[(size_t)Mq*Hq];
__device__ float g_beta[(size_t)Mq*Hq];
__device__ float g_cos[(size_t)Tq*32];
__device__ float g_sin[(size_t)Tq*32];

// ---------------- RoPE (YaRN) cos/sin table ---------------------------------
__global__ void rope_table_kernel(float* __restrict__ ct, float* __restrict__ st) {
    int idx = blockIdx.x * blockDim.x + threadIdx.x;
    if (idx >= Tq * 32) return;
    int t = idx >> 5;
    int i = idx & 31;
    double ar = (double)i / 32.0;
    double scaled_base = 10000.0 * pow(32.0, 64.0 / 62.0);
    double inv_freq = pow(scaled_base, -ar);
    double wavelen = 2.0 * M_PI * pow(10000.0, ar);
    double mscale = (wavelen - 1.0) / 31.0;
    mscale = mscale < 0.0 ? 0.0 : (mscale > 1.0 ? 1.0 : mscale);
    double scale = 1.0 + 31.0 * mscale;
    float fr = (float)(((double)t / scale) * inv_freq);
    ct[idx] = cosf(fr);
    st[idx] = sinf(fr);
}

// ---------------- SGEMM (NT), f32x2 inner product ---------------------------
#define GBM 128
#define GBN 128
#define GBK 16

__global__ __launch_bounds__(256, 2) void sgemm_nt(
    const float* __restrict__ A, const float* __restrict__ W,
    float* __restrict__ C, int M, int N, int K)
{
    __shared__ __align__(16) float As[GBK][GBM + 4];
    __shared__ __align__(16) float Bs[GBK][GBN + 4];
    const int tid = threadIdx.x;
    const int m0 = blockIdx.x * GBM;
    const int n0 = blockIdx.y * GBN;
    const int tx = tid & 15, ty = tid >> 4;

    const int r0 = tid >> 2;            // 0..63
    const int c0 = (tid & 3) * 4;       // 0,4,8,12

    const float* Aa = A + (size_t)m0 * K;
    const float* Wa = W + (size_t)n0 * K;

    float4 pa0 = *(const float4*)(Aa + (size_t)r0 * K + c0);
    float4 pa1 = *(const float4*)(Aa + (size_t)(r0 + 64) * K + c0);
    float4 pb0 = *(const float4*)(Wa + (size_t)r0 * K + c0);
    float4 pb1 = *(const float4*)(Wa + (size_t)(r0 + 64) * K + c0);

    ull acc2[8][4];
#pragma unroll
    for (int i = 0; i < 8; i++)
#pragma unroll
        for (int j = 0; j < 4; j++) acc2[i][j] = 0ULL;

    const int nk = K / GBK;
    for (int kt = 0; kt < nk; kt++) {
        As[c0 + 0][r0] = pa0.x; As[c0 + 1][r0] = pa0.y;
        As[c0 + 2][r0] = pa0.z; As[c0 + 3][r0] = pa0.w;
        As[c0 + 0][r0 + 64] = pa1.x; As[c0 + 1][r0 + 64] = pa1.y;
        As[c0 + 2][r0 + 64] = pa1.z; As[c0 + 3][r0 + 64] = pa1.w;
        Bs[c0 + 0][r0] = pb0.x; Bs[c0 + 1][r0] = pb0.y;
        Bs[c0 + 2][r0] = pb0.z; Bs[c0 + 3][r0] = pb0.w;
        Bs[c0 + 0][r0 + 64] = pb1.x; Bs[c0 + 1][r0 + 64] = pb1.y;
        Bs[c0 + 2][r0 + 64] = pb1.z; Bs[c0 + 3][r0 + 64] = pb1.w;
        __syncthreads();

        if (kt + 1 < nk) {
            int kb = (kt + 1) * GBK + c0;
            pa0 = *(const float4*)(Aa + (size_t)r0 * K + kb);
            pa1 = *(const float4*)(Aa + (size_t)(r0 + 64) * K + kb);
            pb0 = *(const float4*)(Wa + (size_t)r0 * K + kb);
            pb1 = *(const float4*)(Wa + (size_t)(r0 + 64) * K + kb);
        }

#pragma unroll
        for (int kk = 0; kk < GBK; kk++) {
            const float4* ap = (const float4*)&As[kk][ty * 8];
            float4 a0 = ap[0], a1 = ap[1];
            const longlong2* bp = (const longlong2*)&Bs[kk][tx * 8];
            longlong2 bl0 = bp[0], bl1 = bp[1];
            ull b2[4];
            b2[0] = (ull)bl0.x; b2[1] = (ull)bl0.y;
            b2[2] = (ull)bl1.x; b2[3] = (ull)bl1.y;
            float av[8] = {a0.x, a0.y, a0.z, a0.w, a1.x, a1.y, a1.z, a1.w};
#pragma unroll
            for (int i = 0; i < 8; i++) {
                ull ai = pack2(av[i], av[i]);
#pragma unroll
                for (int j = 0; j < 4; j++)
                    acc2[i][j] = ffma2(ai, b2[j], acc2[i][j]);
            }
        }
        __syncthreads();
    }

#pragma unroll
    for (int i = 0; i < 8; i++) {
        float* Cp = C + (size_t)(m0 + ty * 8 + i) * N + n0 + tx * 8;
        float2 u0 = unpack2(acc2[i][0]);
        float2 u1 = unpack2(acc2[i][1]);
        float2 u2 = unpack2(acc2[i][2]);
        float2 u3 = unpack2(acc2[i][3]);
        *(float4*)Cp       = make_float4(u0.x, u0.y, u1.x, u1.y);
        *(float4*)(Cp + 4) = make_float4(u2.x, u2.y, u3.x, u3.y);
    }
}

// ---------------- beta / alpha (small GEMM N=32 + transforms) ----------------
__global__ __launch_bounds__(128) void bg_kernel(
    const float* __restrict__ x,
    const float* __restrict__ Wb, const float* __restrict__ bb,
    const float* __restrict__ Wgk, const float* __restrict__ bgk,
    const float* __restrict__ A_log, const float* __restrict__ dt_bias,
    float* __restrict__ beta, float* __restrict__ alpha)
{
    __shared__ float xs[Cq];
    const int m = blockIdx.x;
    const float4* xr = (const float4*)(x + (size_t)m * Cq);
    for (int i = threadIdx.x; i < Cq / 4; i += 128) ((float4*)xs)[i] = xr[i];
    __syncthreads();

    int warp = threadIdx.x >> 5, lane = threadIdx.x & 31;
#pragma unroll
    for (int nn = 0; nn < 8; nn++) {
        int n = warp * 8 + nn;
        const float* wr = (n < 16) ? (Wb + (size_t)n * Cq) : (Wgk + (size_t)(n - 16) * Cq);
        float acc = 0.f;
#pragma unroll 8
        for (int c = lane; c < Cq; c += 32) acc += xs[c] * __ldg(wr + c);
#pragma unroll
        for (int s = 16; s > 0; s >>= 1) acc += __shfl_xor_sync(0xffffffffu, acc, s);
        if (lane == 0) {
            if (n < 16) {
                beta[(size_t)m * Hq + n] = 1.f / (1.f + expf(-(acc + bb[n])));
            } else {
                int hh = n - 16;
                float gv = acc + bgk[hh] + dt_bias[hh];
                float sp = (gv > 20.f) ? gv : log1pf(expf(gv));
                alpha[(size_t)m * Hq + hh] = expf(-expf(A_log[hh]) * sp);
            }
        }
    }
}

// ---------------- conv(K=4)+silu, then RoPE + l2norm for q,k -----------------
__device__ __forceinline__ float conv_silu(const float* __restrict__ pre,
                                           const float* __restrict__ w,
                                           const float* __restrict__ bias,
                                           int b, int t, int c)
{
    float acc = bias[c];
#pragma unroll
    for (int i = 0; i < 4; i++) {
        int tt = t - 3 + i;
        if (tt >= 0) acc = fmaf(pre[((size_t)b * Tq + tt) * Cq + c], w[c * 4 + i], acc);
    }
    return acc / (1.f + expf(-acc));
}

__global__ __launch_bounds__(64) void conv_rope_kernel(
    const float* __restrict__ qpre, const float* __restrict__ kpre,
    const float* __restrict__ vpre,
    const float* __restrict__ cqw, const float* __restrict__ cqb,
    const float* __restrict__ ckw, const float* __restrict__ ckb,
    const float* __restrict__ cvw, const float* __restrict__ cvb,
    const float* __restrict__ ct, const float* __restrict__ st,
    float* __restrict__ qo, float* __restrict__ ko, float* __restrict__ vo)
{
    const int blk = blockIdx.x;                 // b*T*H
    const int b = blk / (Tq * Hq);
    const int rem = blk % (Tq * Hq);
    const int t = rem / Hq;
    const int h = rem % Hq;
    const int d = threadIdx.x;                  // 0..63
    const int c = h * Dq + d;
    const size_t gidx = ((size_t)b * Tq + t) * Cq + c;

    __shared__ float sq[64], sk[64], redq[2], redk[2];

    vo[gidx] = conv_silu(vpre, cvw, cvb, b, t, c);
    sq[d] = conv_silu(qpre, cqw, cqb, b, t, c);
    sk[d] = conv_silu(kpre, ckw, ckb, b, t, c);
    __syncthreads();

    int j = d & 31;
    int ci = (2 * j) & 31;
    float ce = ct[(size_t)t * 32 + ci];
    float se = st[(size_t)t * 32 + ci];
    float q1 = sq[2 * j], q2 = sq[2 * j + 1];
    float k1 = sk[2 * j], k2 = sk[2 * j + 1];
    float rq = (d < 32) ? (q1 * ce - q2 * se) : (q1 * se + q2 * ce);
    float rk = (d < 32) ? (k1 * ce - k2 * se) : (k1 * se + k2 * ce);

    float sq2 = rq * rq, sk2 = rk * rk;
#pragma unroll
    for (int s = 16; s > 0; s >>= 1) {
        sq2 += __shfl_xor_sync(0xffffffffu, sq2, s);
        sk2 += __shfl_xor_sync(0xffffffffu, sk2, s);
    }
    int wid = d >> 5;
    if ((d & 31) == 0) { redq[wid] = sq2; redk[wid] = sk2; }
    __syncthreads();
    float qn = redq[0] + redq[1];
    float kn = redk[0] + redk[1];
    float qinv = 1.f / fmaxf(sqrtf(qn), 1e-12f);
    float kinv = 1.f / fmaxf(sqrtf(kn), 1e-12f);
    qo[gidx] = rq * qinv;
    ko[gidx] = rk * kinv;
}

// ---------------- sequential gated-delta scan + fused epilogue ---------------
// 256 threads: thread = (vr = tid>>2, kg = tid&3). Each thread owns 16 k-cols
// of S[vr][*] packed as 8 f32x2. One __syncthreads per step; everything for
// t+1 (q,k,v,gate,alpha,beta) is prefetched via registers into double-buffered
// smem, so no dependent global-load latency sits on the critical path.
__global__ __launch_bounds__(256, 1) void scan_kernel(
    const float* __restrict__ q, const float* __restrict__ k,
    const float* __restrict__ v,
    const float* __restrict__ alpha, const float* __restrict__ beta,
    const float* __restrict__ gate, const float* __restrict__ Dp,
    const float* __restrict__ o_norm_w, float* __restrict__ og)
{
    const int bh = blockIdx.x;          // 0..31
    const int b = bh >> 4;
    const int h = bh & 15;
    const int tid = threadIdx.x;
    const int vr = tid >> 2;            // v row 0..63
    const int kg = tid & 3;             // k group (16 cols each)
    const int lane = tid & 31;
    const int wid = tid >> 5;

    __shared__ __align__(16) float qs[2][64], ks[2][64], vs[2][64], gs[2][64];
    __shared__ float ab[2][2];
    __shared__ float red[2][8];

    ull S2[8];
#pragma unroll
    for (int j = 0; j < 8; j++) S2[j] = 0ULL;

    const float dp = Dp[h];
    const float wnv = o_norm_w[vr];
    const size_t base = (size_t)b * Tq * Cq + h * Dq;
    const size_t abbase = (size_t)b * Tq * Hq + h;

    if (tid < 64) {
        qs[0][tid] = q[base + tid];
        ks[0][tid] = k[base + tid];
        vs[0][tid] = v[base + tid];
        gs[0][tid] = gate[base + tid];
    }
    if (tid == 0) { ab[0][0] = alpha[abbase]; ab[0][1] = beta[abbase]; }
    __syncthreads();

    float nq = 0.f, nk = 0.f, nv = 0.f, ng = 0.f, na = 0.f, nb = 0.f;

    for (int t = 0; t < Tq; t++) {
        const int cur = t & 1, nxt = cur ^ 1;

        // issue prefetch LDGs for t+1 as early as possible
        if (t + 1 < Tq) {
            size_t off = base + (size_t)(t + 1) * Cq;
            if (tid < 64) {
                nq = q[off + tid]; nk = k[off + tid];
                nv = v[off + tid]; ng = gate[off + tid];
            }
            if (tid == 0) {
                size_t abo = abbase + (size_t)(t + 1) * Hq;
                na = alpha[abo]; nb = beta[abo];
            }
        }

        const float a = ab[cur][0], bt = ab[cur][1];
        const float vv = vs[cur][vr];

        ull k2[8], q2[8];
        {
            const longlong2* kp = (const longlong2*)(&ks[cur][kg * 16]);
            const longlong2* qp = (const longlong2*)(&qs[cur][kg * 16]);
#pragma unroll
            for (int j = 0; j < 4; j++) {
                longlong2 kv = kp[j], qv = qp[j];
                k2[2 * j] = (ull)kv.x; k2[2 * j + 1] = (ull)kv.y;
                q2[2 * j] = (ull)qv.x; q2[2 * j + 1] = (ull)qv.y;
            }
        }

        // p = (S k)[vr]
        ull pA = 0ULL, pB = 0ULL;
#pragma unroll
        for (int j = 0; j < 4; j++) {
            pA = ffma2(S2[j], k2[j], pA);
            pB = ffma2(S2[j + 4], k2[j + 4], pB);
        }
        float2 pu = unpack2(fadd2(pA, pB));
        float p = pu.x + pu.y;
        p += __shfl_xor_sync(0xffffffffu, p, 1);
        p += __shfl_xor_sync(0xffffffffu, p, 2);

        const float coef = bt * vv - a * bt * p;
        const ull c2 = pack2(coef, coef);
        const ull a2 = pack2(a, a);

        ull oA = 0ULL, oB = 0ULL;
#pragma unroll
        for (int j = 0; j < 4; j++) {
            S2[j] = ffma2(a2, S2[j], fmul2(c2, k2[j]));
            oA = ffma2(S2[j], q2[j], oA);
            S2[j + 4] = ffma2(a2, S2[j + 4], fmul2(c2, k2[j + 4]));
            oB = ffma2(S2[j + 4], q2[j + 4], oB);
        }
        float2 ou = unpack2(fadd2(oA, oB));
        float o = ou.x + ou.y;
        o += __shfl_xor_sync(0xffffffffu, o, 1);
        o += __shfl_xor_sync(0xffffffffu, o, 2);

        const float val = o + dp * vv;
        float sq = val * val * 0.25f;
#pragma unroll
        for (int s = 16; s > 0; s >>= 1) sq += __shfl_xor_sync(0xffffffffu, sq, s);
        if (lane == 0) red[cur][wid] = sq;

        // stage prefetched t+1 into smem
        if (t + 1 < Tq) {
            if (tid < 64) {
                qs[nxt][tid] = nq; ks[nxt][tid] = nk;
                vs[nxt][tid] = nv; gs[nxt][tid] = ng;
            }
            if (tid == 0) { ab[nxt][0] = na; ab[nxt][1] = nb; }
        }
        __syncthreads();

        const float ssum = red[cur][0] + red[cur][1] + red[cur][2] + red[cur][3]
                         + red[cur][4] + red[cur][5] + red[cur][6] + red[cur][7];
        if (kg == 0) {
            float ms = ssum * (1.f / 64.f);
            float y = val * rsqrtf(ms + EPSq) * wnv;
            float sil = y / (1.f + expf(-y));
            og[base + (size_t)t * Cq + vr] = gs[cur][vr] * sil;
        }
    }
}

// ---------------- launch ------------------------------------------------------
extern "C" void kernel_launch(void* const* d_in, const int* in_sizes, int n_in,
                              void* d_out, int out_size)
{
    const float* x    = (const float*)d_in[0];
    const float* Wq   = (const float*)d_in[1];
    const float* Wk   = (const float*)d_in[2];
    const float* Wv   = (const float*)d_in[3];
    const float* Wg   = (const float*)d_in[4];
    const float* Wo   = (const float*)d_in[5];
    const float* Wb   = (const float*)d_in[6];
    const float* bb   = (const float*)d_in[7];
    const float* Wgk  = (const float*)d_in[8];
    const float* bgk  = (const float*)d_in[9];
    const float* cqw  = (const float*)d_in[10];
    const float* cqb  = (const float*)d_in[11];
    const float* ckw  = (const float*)d_in[12];
    const float* ckb  = (const float*)d_in[13];
    const float* cvw  = (const float*)d_in[14];
    const float* cvb  = (const float*)d_in[15];
    const float* A_log = (const float*)d_in[16];
    const float* Dp   = (const float*)d_in[17];
    const float* dtb  = (const float*)d_in[18];
    const float* onw  = (const float*)d_in[19];
    float* out = (float*)d_out;

    float *qpre, *kpre, *vpre, *gbuf, *qn, *kn, *vn, *ogb, *al, *be, *ct, *st;
    cudaGetSymbolAddress((void**)&qpre, g_qpre);
    cudaGetSymbolAddress((void**)&kpre, g_kpre);
    cudaGetSymbolAddress((void**)&vpre, g_vpre);
    cudaGetSymbolAddress((void**)&gbuf, g_gate);
    cudaGetSymbolAddress((void**)&qn,   g_q);
    cudaGetSymbolAddress((void**)&kn,   g_k);
    cudaGetSymbolAddress((void**)&vn,   g_v);
    cudaGetSymbolAddress((void**)&ogb,  g_og);
    cudaGetSymbolAddress((void**)&al,   g_alpha);
    cudaGetSymbolAddress((void**)&be,   g_beta);
    cudaGetSymbolAddress((void**)&ct,   g_cos);
    cudaGetSymbolAddress((void**)&st,   g_sin);

    rope_table_kernel<<<(Tq * 32 + 255) / 256, 256>>>(ct, st);

    dim3 gg(Mq / GBM, Cq / GBN);
    sgemm_nt<<<gg, 256>>>(x, Wq, qpre, Mq, Cq, Cq);
    sgemm_nt<<<gg, 256>>>(x, Wk, kpre, Mq, Cq, Cq);
    sgemm_nt<<<gg, 256>>>(x, Wv, vpre, Mq, Cq, Cq);
    sgemm_nt<<<gg, 256>>>(x, Wg, gbuf, Mq, Cq, Cq);

    bg_kernel<<<Mq, 128>>>(x, Wb, bb, Wgk, bgk, A_log, dtb, be, al);

    conv_rope_kernel<<<Bq * Tq * Hq, 64>>>(qpre, kpre, vpre,
                                           cqw, cqb, ckw, ckb, cvw, cvb,
                                           ct, st, qn, kn, vn);

    scan_kernel<<<Bq * Hq, 256>>>(qn, kn, vn, al, be, gbuf, Dp, onw, ogb);

    sgemm_nt<<<gg, 256>>>(ogb, Wo, out, Mq, Cq, Cq);
}

// round 3
// speedup vs baseline: 2.2955x; 2.1938x over previous
#include <cuda_runtime.h>
#include <cuda_bf16.h>
#include <math.h>

#define Bq 2
#define Tq 2048
#define Cq 1024
#define Hq 16
#define Dq 64
#define Mq (Bq*Tq)          // 4096
#define EPSq 1e-6f
#define CHUNK 16
#define NCH (Tq/CHUNK)      // 128
#define VSEG 8              // v-rows per scan block
#define NSEG (Dq/VSEG)      // 8 blocks per (b,h)

typedef unsigned long long ull;

// ---------------- packed f32x2 helpers (Blackwell FFMA2) ---------------------
__device__ __forceinline__ ull ffma2(ull a, ull b, ull c) {
    ull d; asm("fma.rn.f32x2 %0, %1, %2, %3;" : "=l"(d) : "l"(a), "l"(b), "l"(c)); return d;
}
__device__ __forceinline__ ull fmul2(ull a, ull b) {
    ull d; asm("mul.rn.f32x2 %0, %1, %2;" : "=l"(d) : "l"(a), "l"(b)); return d;
}
__device__ __forceinline__ ull fadd2(ull a, ull b) {
    ull d; asm("add.rn.f32x2 %0, %1, %2;" : "=l"(d) : "l"(a), "l"(b)); return d;
}
__device__ __forceinline__ ull pack2(float x, float y) {
    ull d; asm("mov.b64 %0, {%1, %2};" : "=l"(d) : "f"(x), "f"(y)); return d;
}
__device__ __forceinline__ float2 unpack2(ull v) {
    float x, y; asm("mov.b64 {%0, %1}, %2;" : "=f"(x), "=f"(y) : "l"(v));
    return make_float2(x, y);
}
__device__ __forceinline__ void cpa16(void* s, const void* g) {
    asm volatile("cp.async.cg.shared.global [%0], [%1], 16;"
        :: "r"((unsigned)__cvta_generic_to_shared(s)), "l"(g));
}
#define CP_COMMIT() asm volatile("cp.async.commit_group;")
#define CP_WAIT1()  asm volatile("cp.async.wait_group 1;")

// ---------------- scratch (static device globals; no allocation) -------------
__device__ float g_qpre[(size_t)Mq*Cq];
__device__ float g_kpre[(size_t)Mq*Cq];
__device__ float g_vpre[(size_t)Mq*Cq];
__device__ float g_gate[(size_t)Mq*Cq];
__device__ float g_q[(size_t)Mq*Cq];
__device__ float g_k[(size_t)Mq*Cq];
__device__ float g_v[(size_t)Mq*Cq];
__device__ float g_og[(size_t)Mq*Cq];
__device__ float g_alT[(size_t)Mq*Hq];   // [b*H+h][t] transposed
__device__ float g_beT[(size_t)Mq*Hq];
__device__ float g_cos[(size_t)Tq*32];
__device__ float g_sin[(size_t)Tq*32];

// ---------------- RoPE (YaRN) cos/sin table ---------------------------------
__global__ void rope_table_kernel(float* __restrict__ ct, float* __restrict__ st) {
    int idx = blockIdx.x * blockDim.x + threadIdx.x;
    if (idx >= Tq * 32) return;
    int t = idx >> 5;
    int i = idx & 31;
    double ar = (double)i / 32.0;
    double scaled_base = 10000.0 * pow(32.0, 64.0 / 62.0);
    double inv_freq = pow(scaled_base, -ar);
    double wavelen = 2.0 * M_PI * pow(10000.0, ar);
    double mscale = (wavelen - 1.0) / 31.0;
    mscale = mscale < 0.0 ? 0.0 : (mscale > 1.0 ? 1.0 : mscale);
    double scale = 1.0 + 31.0 * mscale;
    float fr = (float)(((double)t / scale) * inv_freq);
    ct[idx] = cosf(fr);
    st[idx] = sinf(fr);
}

// ---------------- SGEMM (NT), f32x2 inner product ---------------------------
#define GBM 128
#define GBN 128
#define GBK 16

__global__ __launch_bounds__(256, 2) void sgemm_nt(
    const float* __restrict__ A, const float* __restrict__ W,
    float* __restrict__ C, int M, int N, int K)
{
    __shared__ __align__(16) float As[GBK][GBM + 4];
    __shared__ __align__(16) float Bs[GBK][GBN + 4];
    const int tid = threadIdx.x;
    const int m0 = blockIdx.x * GBM;
    const int n0 = blockIdx.y * GBN;
    const int tx = tid & 15, ty = tid >> 4;

    const int r0 = tid >> 2;
    const int c0 = (tid & 3) * 4;

    const float* Aa = A + (size_t)m0 * K;
    const float* Wa = W + (size_t)n0 * K;

    float4 pa0 = *(const float4*)(Aa + (size_t)r0 * K + c0);
    float4 pa1 = *(const float4*)(Aa + (size_t)(r0 + 64) * K + c0);
    float4 pb0 = *(const float4*)(Wa + (size_t)r0 * K + c0);
    float4 pb1 = *(const float4*)(Wa + (size_t)(r0 + 64) * K + c0);

    ull acc2[8][4];
#pragma unroll
    for (int i = 0; i < 8; i++)
#pragma unroll
        for (int j = 0; j < 4; j++) acc2[i][j] = 0ULL;

    const int nk = K / GBK;
    for (int kt = 0; kt < nk; kt++) {
        As[c0 + 0][r0] = pa0.x; As[c0 + 1][r0] = pa0.y;
        As[c0 + 2][r0] = pa0.z; As[c0 + 3][r0] = pa0.w;
        As[c0 + 0][r0 + 64] = pa1.x; As[c0 + 1][r0 + 64] = pa1.y;
        As[c0 + 2][r0 + 64] = pa1.z; As[c0 + 3][r0 + 64] = pa1.w;
        Bs[c0 + 0][r0] = pb0.x; Bs[c0 + 1][r0] = pb0.y;
        Bs[c0 + 2][r0] = pb0.z; Bs[c0 + 3][r0] = pb0.w;
        Bs[c0 + 0][r0 + 64] = pb1.x; Bs[c0 + 1][r0 + 64] = pb1.y;
        Bs[c0 + 2][r0 + 64] = pb1.z; Bs[c0 + 3][r0 + 64] = pb1.w;
        __syncthreads();

        if (kt + 1 < nk) {
            int kb = (kt + 1) * GBK + c0;
            pa0 = *(const float4*)(Aa + (size_t)r0 * K + kb);
            pa1 = *(const float4*)(Aa + (size_t)(r0 + 64) * K + kb);
            pb0 = *(const float4*)(Wa + (size_t)r0 * K + kb);
            pb1 = *(const float4*)(Wa + (size_t)(r0 + 64) * K + kb);
        }

#pragma unroll
        for (int kk = 0; kk < GBK; kk++) {
            const float4* ap = (const float4*)&As[kk][ty * 8];
            float4 a0 = ap[0], a1 = ap[1];
            const longlong2* bp = (const longlong2*)&Bs[kk][tx * 8];
            longlong2 bl0 = bp[0], bl1 = bp[1];
            ull b2[4];
            b2[0] = (ull)bl0.x; b2[1] = (ull)bl0.y;
            b2[2] = (ull)bl1.x; b2[3] = (ull)bl1.y;
            float av[8] = {a0.x, a0.y, a0.z, a0.w, a1.x, a1.y, a1.z, a1.w};
#pragma unroll
            for (int i = 0; i < 8; i++) {
                ull ai = pack2(av[i], av[i]);
#pragma unroll
                for (int j = 0; j < 4; j++)
                    acc2[i][j] = ffma2(ai, b2[j], acc2[i][j]);
            }
        }
        __syncthreads();
    }

#pragma unroll
    for (int i = 0; i < 8; i++) {
        float* Cp = C + (size_t)(m0 + ty * 8 + i) * N + n0 + tx * 8;
        float2 u0 = unpack2(acc2[i][0]);
        float2 u1 = unpack2(acc2[i][1]);
        float2 u2 = unpack2(acc2[i][2]);
        float2 u3 = unpack2(acc2[i][3]);
        *(float4*)Cp       = make_float4(u0.x, u0.y, u1.x, u1.y);
        *(float4*)(Cp + 4) = make_float4(u2.x, u2.y, u3.x, u3.y);
    }
}

// ---------------- beta / alpha (small GEMM N=32), transposed outputs ---------
__global__ __launch_bounds__(128) void bg_kernel(
    const float* __restrict__ x,
    const float* __restrict__ Wb, const float* __restrict__ bb,
    const float* __restrict__ Wgk, const float* __restrict__ bgk,
    const float* __restrict__ A_log, const float* __restrict__ dt_bias,
    float* __restrict__ beT, float* __restrict__ alT)
{
    __shared__ float xs[Cq];
    const int m = blockIdx.x;
    const int b = m >> 11;          // T = 2048
    const int t = m & 2047;
    const float4* xr = (const float4*)(x + (size_t)m * Cq);
    for (int i = threadIdx.x; i < Cq / 4; i += 128) ((float4*)xs)[i] = xr[i];
    __syncthreads();

    int warp = threadIdx.x >> 5, lane = threadIdx.x & 31;
#pragma unroll
    for (int nn = 0; nn < 8; nn++) {
        int n = warp * 8 + nn;
        const float* wr = (n < 16) ? (Wb + (size_t)n * Cq) : (Wgk + (size_t)(n - 16) * Cq);
        float acc = 0.f;
#pragma unroll 8
        for (int c = lane; c < Cq; c += 32) acc += xs[c] * __ldg(wr + c);
#pragma unroll
        for (int s = 16; s > 0; s >>= 1) acc += __shfl_xor_sync(0xffffffffu, acc, s);
        if (lane == 0) {
            if (n < 16) {
                beT[((size_t)b * Hq + n) * Tq + t] = 1.f / (1.f + expf(-(acc + bb[n])));
            } else {
                int hh = n - 16;
                float gv = acc + bgk[hh] + dt_bias[hh];
                float sp = (gv > 20.f) ? gv : log1pf(expf(gv));
                alT[((size_t)b * Hq + hh) * Tq + t] = expf(-expf(A_log[hh]) * sp);
            }
        }
    }
}

// ---------------- conv(K=4)+silu, then RoPE + l2norm for q,k -----------------
__device__ __forceinline__ float conv_silu(const float* __restrict__ pre,
                                           const float* __restrict__ w,
                                           const float* __restrict__ bias,
                                           int b, int t, int c)
{
    float acc = bias[c];
#pragma unroll
    for (int i = 0; i < 4; i++) {
        int tt = t - 3 + i;
        if (tt >= 0) acc = fmaf(pre[((size_t)b * Tq + tt) * Cq + c], w[c * 4 + i], acc);
    }
    return acc / (1.f + expf(-acc));
}

__global__ __launch_bounds__(64) void conv_rope_kernel(
    const float* __restrict__ qpre, const float* __restrict__ kpre,
    const float* __restrict__ vpre,
    const float* __restrict__ cqw, const float* __restrict__ cqb,
    const float* __restrict__ ckw, const float* __restrict__ ckb,
    const float* __restrict__ cvw, const float* __restrict__ cvb,
    const float* __restrict__ ct, const float* __restrict__ st,
    float* __restrict__ qo, float* __restrict__ ko, float* __restrict__ vo)
{
    const int blk = blockIdx.x;
    const int b = blk / (Tq * Hq);
    const int rem = blk % (Tq * Hq);
    const int t = rem / Hq;
    const int h = rem % Hq;
    const int d = threadIdx.x;
    const int c = h * Dq + d;
    const size_t gidx = ((size_t)b * Tq + t) * Cq + c;

    __shared__ float sq[64], sk[64], redq[2], redk[2];

    vo[gidx] = conv_silu(vpre, cvw, cvb, b, t, c);
    sq[d] = conv_silu(qpre, cqw, cqb, b, t, c);
    sk[d] = conv_silu(kpre, ckw, ckb, b, t, c);
    __syncthreads();

    int j = d & 31;
    int ci = (2 * j) & 31;
    float ce = ct[(size_t)t * 32 + ci];
    float se = st[(size_t)t * 32 + ci];
    float q1 = sq[2 * j], q2 = sq[2 * j + 1];
    float k1 = sk[2 * j], k2 = sk[2 * j + 1];
    float rq = (d < 32) ? (q1 * ce - q2 * se) : (q1 * se + q2 * ce);
    float rk = (d < 32) ? (k1 * ce - k2 * se) : (k1 * se + k2 * ce);

    float sq2 = rq * rq, sk2 = rk * rk;
#pragma unroll
    for (int s = 16; s > 0; s >>= 1) {
        sq2 += __shfl_xor_sync(0xffffffffu, sq2, s);
        sk2 += __shfl_xor_sync(0xffffffffu, sk2, s);
    }
    int wid = d >> 5;
    if ((d & 31) == 0) { redq[wid] = sq2; redk[wid] = sk2; }
    __syncthreads();
    float qn = redq[0] + redq[1];
    float kn = redk[0] + redk[1];
    float qinv = 1.f / fmaxf(sqrtf(qn), 1e-12f);
    float kinv = 1.f / fmaxf(sqrtf(kn), 1e-12f);
    qo[gidx] = rq * qinv;
    ko[gidx] = rk * kinv;
}

// ---------------- sequential gated-delta scan -------------------------------
// One warp per (b, h, v-segment of 8 rows). lane = (vr = lane>>2, kg = lane&3);
// each thread owns 16 k-cols of its row as 8 f32x2. Chunked (16-step) cp.async
// double-buffered smem staging; no __syncthreads anywhere. Writes raw
// val = o + Dp*v; rmsnorm/silu/gate happen in epi_kernel.
__global__ __launch_bounds__(32, 8) void scan_kernel(
    const float* __restrict__ q, const float* __restrict__ k,
    const float* __restrict__ v,
    const float* __restrict__ alT, const float* __restrict__ beT,
    const float* __restrict__ Dp, float* __restrict__ valout)
{
    const int blk = blockIdx.x;
    const int bh = blk >> 3;            // 0..31
    const int seg = blk & 7;
    const int b = bh >> 4;
    const int h = bh & 15;
    const int lane = threadIdx.x;
    const int vr = lane >> 2;           // local v row 0..7
    const int kg = lane & 3;            // k group of 16

    __shared__ __align__(16) float sQ[2][CHUNK][64];
    __shared__ __align__(16) float sK[2][CHUNK][64];
    __shared__ __align__(16) float sV[2][CHUNK][VSEG];
    __shared__ __align__(16) float sA[2][CHUNK];
    __shared__ __align__(16) float sB[2][CHUNK];

    const size_t base  = (size_t)b * Tq * Cq + h * Dq;
    const size_t vbase = base + seg * VSEG;
    const size_t abb   = (size_t)bh * Tq;

    auto load_chunk = [&](int c, int stg) {
        const size_t rowoff = (size_t)c * CHUNK * Cq;
        // q,k: 16 rows x 64 floats = 256 float4, 8 per lane
#pragma unroll
        for (int it = 0; it < 8; it++) {
            int idx = it * 32 + lane;
            int row = idx >> 4;
            int col = (idx & 15) * 4;
            cpa16(&sQ[stg][row][col], q + base + rowoff + (size_t)row * Cq + col);
            cpa16(&sK[stg][row][col], k + base + rowoff + (size_t)row * Cq + col);
        }
        // v: 16 rows x 8 floats = 32 float4, 1 per lane
        {
            int row = lane >> 1;
            int col = (lane & 1) * 4;
            cpa16(&sV[stg][row][col], v + vbase + rowoff + (size_t)row * Cq + col);
        }
        // alpha/beta: 16 floats each = 4 float4 each
        if (lane < 4)      cpa16(&sA[stg][lane * 4], alT + abb + c * CHUNK + lane * 4);
        else if (lane < 8) cpa16(&sB[stg][(lane - 4) * 4], beT + abb + c * CHUNK + (lane - 4) * 4);
    };

    ull S2[8];
#pragma unroll
    for (int j = 0; j < 8; j++) S2[j] = 0ULL;
    const float dp = Dp[h];

    load_chunk(0, 0); CP_COMMIT();
    load_chunk(1, 1); CP_COMMIT();
    CP_WAIT1();
    __syncwarp();

    for (int c = 0; c < NCH; c++) {
        const int stg = c & 1;
#pragma unroll 2
        for (int s = 0; s < CHUNK; s++) {
            const float a  = sA[stg][s];
            const float bt = sB[stg][s];
            const float vv = sV[stg][s][vr];

            ull k2[8], q2[8];
            const ull* kp = (const ull*)&sK[stg][s][kg * 16];
            const ull* qp = (const ull*)&sQ[stg][s][kg * 16];
#pragma unroll
            for (int j = 0; j < 8; j++) { k2[j] = kp[j]; q2[j] = qp[j]; }

            // p = (S k)[vr]
            ull pA = 0ULL, pB = 0ULL;
#pragma unroll
            for (int j = 0; j < 4; j++) {
                pA = ffma2(S2[j], k2[j], pA);
                pB = ffma2(S2[j + 4], k2[j + 4], pB);
            }
            float2 pu = unpack2(fadd2(pA, pB));
            float p = pu.x + pu.y;
            p += __shfl_xor_sync(0xffffffffu, p, 1);
            p += __shfl_xor_sync(0xffffffffu, p, 2);

            const float coef = bt * vv - a * bt * p;
            const ull c2 = pack2(coef, coef);
            const ull a2 = pack2(a, a);

            ull oA = 0ULL, oB = 0ULL;
#pragma unroll
            for (int j = 0; j < 4; j++) {
                S2[j] = ffma2(a2, S2[j], fmul2(c2, k2[j]));
                oA = ffma2(S2[j], q2[j], oA);
                S2[j + 4] = ffma2(a2, S2[j + 4], fmul2(c2, k2[j + 4]));
                oB = ffma2(S2[j + 4], q2[j + 4], oB);
            }
            float2 ou = unpack2(fadd2(oA, oB));
            float o = ou.x + ou.y;
            o += __shfl_xor_sync(0xffffffffu, o, 1);
            o += __shfl_xor_sync(0xffffffffu, o, 2);

            if (kg == 0) {
                float val = fmaf(dp, vv, o);
                valout[vbase + (size_t)(c * CHUNK + s) * Cq + vr] = val;
            }
        }
        if (c + 2 < NCH) load_chunk(c + 2, stg);
        CP_COMMIT();
        CP_WAIT1();
        __syncwarp();
    }
}

// ---------------- epilogue: rmsnorm(D) -> silu -> * gate ---------------------
// one warp per (b,t,h) row of 64; each lane handles 2 elements (float2)
__global__ __launch_bounds__(256) void epi_kernel(
    const float* __restrict__ val, const float* __restrict__ gate,
    const float* __restrict__ onw, float* __restrict__ out)
{
    const int gw = blockIdx.x * 8 + (threadIdx.x >> 5);
    const int lane = threadIdx.x & 31;
    const size_t off = (size_t)gw * 64 + lane * 2;
    float2 vl = *(const float2*)(val + off);
    float ss = vl.x * vl.x + vl.y * vl.y;
#pragma unroll
    for (int s = 16; s > 0; s >>= 1) ss += __shfl_xor_sync(0xffffffffu, ss, s);
    float r = rsqrtf(ss * (1.f / 64.f) + EPSq);
    float2 w2 = *(const float2*)(onw + lane * 2);
    float2 g2 = *(const float2*)(gate + off);
    float y0 = vl.x * r * w2.x;
    float y1 = vl.y * r * w2.y;
    float o0 = g2.x * (y0 / (1.f + expf(-y0)));
    float o1 = g2.y * (y1 / (1.f + expf(-y1)));
    *(float2*)(out + off) = make_float2(o0, o1);
}

// ---------------- launch ------------------------------------------------------
extern "C" void kernel_launch(void* const* d_in, const int* in_sizes, int n_in,
                              void* d_out, int out_size)
{
    const float* x    = (const float*)d_in[0];
    const float* Wq   = (const float*)d_in[1];
    const float* Wk   = (const float*)d_in[2];
    const float* Wv   = (const float*)d_in[3];
    const float* Wg   = (const float*)d_in[4];
    const float* Wo   = (const float*)d_in[5];
    const float* Wb   = (const float*)d_in[6];
    const float* bb   = (const float*)d_in[7];
    const float* Wgk  = (const float*)d_in[8];
    const float* bgk  = (const float*)d_in[9];
    const float* cqw  = (const float*)d_in[10];
    const float* cqb  = (const float*)d_in[11];
    const float* ckw  = (const float*)d_in[12];
    const float* ckb  = (const float*)d_in[13];
    const float* cvw  = (const float*)d_in[14];
    const float* cvb  = (const float*)d_in[15];
    const float* A_log = (const float*)d_in[16];
    const float* Dp   = (const float*)d_in[17];
    const float* dtb  = (const float*)d_in[18];
    const float* onw  = (const float*)d_in[19];
    float* out = (float*)d_out;

    float *qpre, *kpre, *vpre, *gbuf, *qn, *kn, *vn, *ogb, *al, *be, *ct, *st;
    cudaGetSymbolAddress((void**)&qpre, g_qpre);
    cudaGetSymbolAddress((void**)&kpre, g_kpre);
    cudaGetSymbolAddress((void**)&vpre, g_vpre);
    cudaGetSymbolAddress((void**)&gbuf, g_gate);
    cudaGetSymbolAddress((void**)&qn,   g_q);
    cudaGetSymbolAddress((void**)&kn,   g_k);
    cudaGetSymbolAddress((void**)&vn,   g_v);
    cudaGetSymbolAddress((void**)&ogb,  g_og);
    cudaGetSymbolAddress((void**)&al,   g_alT);
    cudaGetSymbolAddress((void**)&be,   g_beT);
    cudaGetSymbolAddress((void**)&ct,   g_cos);
    cudaGetSymbolAddress((void**)&st,   g_sin);

    rope_table_kernel<<<(Tq * 32 + 255) / 256, 256>>>(ct, st);

    dim3 gg(Mq / GBM, Cq / GBN);
    sgemm_nt<<<gg, 256>>>(x, Wq, qpre, Mq, Cq, Cq);
    sgemm_nt<<<gg, 256>>>(x, Wk, kpre, Mq, Cq, Cq);
    sgemm_nt<<<gg, 256>>>(x, Wv, vpre, Mq, Cq, Cq);
    sgemm_nt<<<gg, 256>>>(x, Wg, gbuf, Mq, Cq, Cq);

    bg_kernel<<<Mq, 128>>>(x, Wb, bb, Wgk, bgk, A_log, dtb, be, al);

    conv_rope_kernel<<<Bq * Tq * Hq, 64>>>(qpre, kpre, vpre,
                                           cqw, cqb, ckw, ckb, cvw, cvb,
                                           ct, st, qn, kn, vn);

    // scan writes raw val into qpre (free after conv_rope)
    scan_kernel<<<Bq * Hq * NSEG, 32>>>(qn, kn, vn, al, be, Dp, qpre);

    epi_kernel<<<(Bq * Tq * Hq) / 8, 256>>>(qpre, gbuf, onw, ogb);

    sgemm_nt<<<gg, 256>>>(ogb, Wo, out, Mq, Cq, Cq);
}

// round 5
// speedup vs baseline: 3.4908x; 1.5207x over previous
#include <cuda_runtime.h>
#include <cuda_bf16.h>
#include <math.h>

#define Bq 2
#define Tq 2048
#define Cq 1024
#define Hq 16
#define Dq 64
#define Mq (Bq*Tq)          // 4096
#define EPSq 1e-6f
#define CHUNK 16
#define NCH (Tq/CHUNK)      // 128
#define VSEG 8
#define NSEG (Dq/VSEG)

typedef unsigned long long ull;
typedef unsigned int u32;

// ---------------- packed f32x2 helpers ---------------------------------------
__device__ __forceinline__ ull ffma2(ull a, ull b, ull c) {
    ull d; asm("fma.rn.f32x2 %0, %1, %2, %3;" : "=l"(d) : "l"(a), "l"(b), "l"(c)); return d;
}
__device__ __forceinline__ ull fmul2(ull a, ull b) {
    ull d; asm("mul.rn.f32x2 %0, %1, %2;" : "=l"(d) : "l"(a), "l"(b)); return d;
}
__device__ __forceinline__ ull fadd2(ull a, ull b) {
    ull d; asm("add.rn.f32x2 %0, %1, %2;" : "=l"(d) : "l"(a), "l"(b)); return d;
}
__device__ __forceinline__ ull pack2(float x, float y) {
    ull d; asm("mov.b64 %0, {%1, %2};" : "=l"(d) : "f"(x), "f"(y)); return d;
}
__device__ __forceinline__ float2 unpack2(ull v) {
    float x, y; asm("mov.b64 {%0, %1}, %2;" : "=f"(x), "=f"(y) : "l"(v));
    return make_float2(x, y);
}
__device__ __forceinline__ void cpa16(void* s, const void* g) {
    asm volatile("cp.async.cg.shared.global [%0], [%1], 16;"
        :: "r"((unsigned)__cvta_generic_to_shared(s)), "l"(g));
}
#define CP_COMMIT() asm volatile("cp.async.commit_group;")
#define CP_WAIT1()  asm volatile("cp.async.wait_group 1;")

// ---------------- mma.sync helpers (sm_80 path, works on plain sm_103) -------
__device__ __forceinline__ void ldsm4(u32* r, u32 addr) {
    asm volatile("ldmatrix.sync.aligned.m8n8.x4.shared.b16 {%0,%1,%2,%3}, [%4];"
        : "=r"(r[0]), "=r"(r[1]), "=r"(r[2]), "=r"(r[3]) : "r"(addr));
}
__device__ __forceinline__ void mma16816(float* d, const u32* a, u32 b0, u32 b1) {
    asm volatile("mma.sync.aligned.m16n8k16.row.col.f32.bf16.bf16.f32 "
        "{%0,%1,%2,%3}, {%4,%5,%6,%7}, {%8,%9}, {%0,%1,%2,%3};"
        : "+f"(d[0]), "+f"(d[1]), "+f"(d[2]), "+f"(d[3])
        : "r"(a[0]), "r"(a[1]), "r"(a[2]), "r"(a[3]), "r"(b0), "r"(b1));
}

// ---------------- scratch ----------------------------------------------------
__device__ float g_qpre[(size_t)Mq*Cq];
__device__ float g_kpre[(size_t)Mq*Cq];
__device__ float g_vpre[(size_t)Mq*Cq];
__device__ float g_gate[(size_t)Mq*Cq];
__device__ float g_q[(size_t)Mq*Cq];
__device__ float g_k[(size_t)Mq*Cq];
__device__ float g_v[(size_t)Mq*Cq];
__device__ float g_alT[(size_t)Mq*Hq];
__device__ float g_beT[(size_t)Mq*Hq];
__device__ float g_cos[(size_t)Tq*32];
__device__ float g_sin[(size_t)Tq*32];
__device__ __nv_bfloat16 g_xhi[(size_t)Mq*Cq];
__device__ __nv_bfloat16 g_xlo[(size_t)Mq*Cq];
__device__ __nv_bfloat16 g_whi[(size_t)5*Cq*Cq];
__device__ __nv_bfloat16 g_wlo[(size_t)5*Cq*Cq];
__device__ __nv_bfloat16 g_oghi[(size_t)Mq*Cq];
__device__ __nv_bfloat16 g_oglo[(size_t)Mq*Cq];

// ---------------- split fp32 -> bf16 hi/lo -----------------------------------
__device__ __forceinline__ void split1(float f, __nv_bfloat16& h, __nv_bfloat16& l) {
    h = __float2bfloat16(f);
    l = __float2bfloat16(f - __bfloat162float(h));
}
__device__ __forceinline__ u32 packbf(__nv_bfloat16 a, __nv_bfloat16 b) {
    return (u32)__bfloat16_as_ushort(a) | ((u32)__bfloat16_as_ushort(b) << 16);
}

__global__ __launch_bounds__(256) void split_kernel(
    const float* __restrict__ in, __nv_bfloat16* __restrict__ hi,
    __nv_bfloat16* __restrict__ lo, int n4)
{
    int i = blockIdx.x * 256 + threadIdx.x;
    if (i >= n4) return;
    float4 v = ((const float4*)in)[i];
    __nv_bfloat16 h0, h1, h2, h3, l0, l1, l2, l3;
    split1(v.x, h0, l0); split1(v.y, h1, l1);
    split1(v.z, h2, l2); split1(v.w, h3, l3);
    ((uint2*)hi)[i] = make_uint2(packbf(h0, h1), packbf(h2, h3));
    ((uint2*)lo)[i] = make_uint2(packbf(l0, l1), packbf(l2, l3));
}

// ---------------- tensor-core split-bf16 GEMM (NT) via mma.sync --------------
// C[m][n] = sum_k A[m][k]*B[n][k]; A,B as bf16 hi/lo. Tile 128x128, BK=32 bf16.
// 8 warps: warp_m = wid&3 (4), warp_n = wid>>2 (2); warp tile 32(m) x 64(n).
// smem tile: 128 rows x 64B, 16B-chunk swizzle: phys = row*4 + (c ^ ((row>>1)&3)).
#define TILE_B 8192                   // one tile (A or B, hi or lo)
#define STG_B (4*TILE_B)              // Ahi|Alo|Bhi|Blo = 32KB
#define NSTG 3
#define TG_SMEM (NSTG*STG_B)

__global__ __launch_bounds__(256, 1) void tgemm_nt(
    const __nv_bfloat16* __restrict__ Ahi, const __nv_bfloat16* __restrict__ Alo,
    const __nv_bfloat16* __restrict__ Bhi, const __nv_bfloat16* __restrict__ Blo,
    float* __restrict__ C, int K, int ldc)
{
    extern __shared__ __align__(1024) char ts[];
    const u32 sbase = (u32)__cvta_generic_to_shared(ts);
    const int tid = threadIdx.x;
    const int wid = tid >> 5;
    const int lane = tid & 31;
    const int warp_m = wid & 3;
    const int warp_n = wid >> 2;
    const int m0 = blockIdx.x * 128;
    const int n0 = blockIdx.y * 128;
    const int nchk = K / 32;

    // ---- global -> smem loader mapping (per thread: 2 chunks per tile) ----
    const int lrow = tid >> 1;
    const int co = (tid & 1) * 2;
    const u32 swl = (lrow >> 1) & 3;
    const u32 so0 = (u32)((lrow * 4 + (co ^ swl)) << 4);
    const u32 so1 = (u32)((lrow * 4 + ((co + 1) ^ swl)) << 4);
    const char* gAh = (const char*)(Ahi + (size_t)(m0 + lrow) * K) + co * 16;
    const char* gAl = (const char*)(Alo + (size_t)(m0 + lrow) * K) + co * 16;
    const char* gBh = (const char*)(Bhi + (size_t)(n0 + lrow) * K) + co * 16;
    const char* gBl = (const char*)(Blo + (size_t)(n0 + lrow) * K) + co * 16;

    auto load_chunk = [&](int c, int stg) {
        const size_t go = (size_t)c * 64;     // 32 bf16 = 64B per chunk
        char* base = ts + stg * STG_B;
        cpa16(base + so0, gAh + go);           cpa16(base + so1, gAh + go + 16);
        cpa16(base + TILE_B + so0, gAl + go);  cpa16(base + TILE_B + so1, gAl + go + 16);
        cpa16(base + 2*TILE_B + so0, gBh + go); cpa16(base + 2*TILE_B + so1, gBh + go + 16);
        cpa16(base + 3*TILE_B + so0, gBl + go); cpa16(base + 3*TILE_B + so1, gBl + go + 16);
    };

    // ---- ldmatrix lane mapping ----
    const int lq = lane >> 3;          // quadrant 0..3
    const int lr = lane & 7;
    const int rowA0 = warp_m * 32 + lr + (lq & 1) * 8;   // + mt*16
    const int rowB0 = warp_n * 64 + lr + (lq & 1) * 8;   // + ntp*16
    const int cq = lq >> 1;            // chunk offset within k16 (0 or 1)

    float acc[2][8][4];
#pragma unroll
    for (int i = 0; i < 2; i++)
#pragma unroll
        for (int j = 0; j < 8; j++)
#pragma unroll
            for (int l = 0; l < 4; l++) acc[i][j][l] = 0.f;

    load_chunk(0, 0); CP_COMMIT();
    load_chunk(1, 1); CP_COMMIT();

    for (int c = 0; c < nchk; c++) {
        const int stg = c % NSTG;
        CP_WAIT1();
        __syncthreads();

        const u32 stb = sbase + stg * STG_B;
#pragma unroll
        for (int ks = 0; ks < 2; ks++) {
            u32 ahf[2][4], alf[2][4], bhf[4][4], blf[4][4];
#pragma unroll
            for (int mt = 0; mt < 2; mt++) {
                int row = rowA0 + mt * 16;
                u32 cc = (u32)(ks * 2 + cq);
                u32 off = (u32)((row * 4 + (cc ^ ((row >> 1) & 3))) << 4);
                ldsm4(ahf[mt], stb + off);
                ldsm4(alf[mt], stb + TILE_B + off);
            }
#pragma unroll
            for (int ntp = 0; ntp < 4; ntp++) {
                int row = rowB0 + ntp * 16;
                u32 cc = (u32)(ks * 2 + cq);
                u32 off = (u32)((row * 4 + (cc ^ ((row >> 1) & 3))) << 4);
                ldsm4(bhf[ntp], stb + 2 * TILE_B + off);
                ldsm4(blf[ntp], stb + 3 * TILE_B + off);
            }
#pragma unroll
            for (int mt = 0; mt < 2; mt++) {
#pragma unroll
                for (int ntp = 0; ntp < 4; ntp++) {
                    // even n-tile: frags {r0, r2}; odd: {r1, r3}
                    mma16816(acc[mt][ntp * 2],     ahf[mt], bhf[ntp][0], bhf[ntp][2]);
                    mma16816(acc[mt][ntp * 2],     ahf[mt], blf[ntp][0], blf[ntp][2]);
                    mma16816(acc[mt][ntp * 2],     alf[mt], bhf[ntp][0], bhf[ntp][2]);
                    mma16816(acc[mt][ntp * 2 + 1], ahf[mt], bhf[ntp][1], bhf[ntp][3]);
                    mma16816(acc[mt][ntp * 2 + 1], ahf[mt], blf[ntp][1], blf[ntp][3]);
                    mma16816(acc[mt][ntp * 2 + 1], alf[mt], bhf[ntp][1], bhf[ntp][3]);
                }
            }
        }

        if (c + 2 < nchk) load_chunk(c + 2, (c + 2) % NSTG);
        CP_COMMIT();
    }

    // ---- epilogue ----
    const int g = lane >> 2;
    const int tg = lane & 3;
#pragma unroll
    for (int mt = 0; mt < 2; mt++) {
        int mrow = m0 + warp_m * 32 + mt * 16 + g;
#pragma unroll
        for (int nt = 0; nt < 8; nt++) {
            int ncol = n0 + warp_n * 64 + nt * 8 + tg * 2;
            *(float2*)(C + (size_t)mrow * ldc + ncol) =
                make_float2(acc[mt][nt][0], acc[mt][nt][1]);
            *(float2*)(C + (size_t)(mrow + 8) * ldc + ncol) =
                make_float2(acc[mt][nt][2], acc[mt][nt][3]);
        }
    }
}

// ---------------- RoPE (YaRN) cos/sin table ----------------------------------
__global__ void rope_table_kernel(float* __restrict__ ct, float* __restrict__ st) {
    int idx = blockIdx.x * blockDim.x + threadIdx.x;
    if (idx >= Tq * 32) return;
    int t = idx >> 5;
    int i = idx & 31;
    double ar = (double)i / 32.0;
    double scaled_base = 10000.0 * pow(32.0, 64.0 / 62.0);
    double inv_freq = pow(scaled_base, -ar);
    double wavelen = 2.0 * M_PI * pow(10000.0, ar);
    double mscale = (wavelen - 1.0) / 31.0;
    mscale = mscale < 0.0 ? 0.0 : (mscale > 1.0 ? 1.0 : mscale);
    double scale = 1.0 + 31.0 * mscale;
    float fr = (float)(((double)t / scale) * inv_freq);
    ct[idx] = cosf(fr);
    st[idx] = sinf(fr);
}

// ---------------- beta / alpha ----------------------------------------------
__global__ __launch_bounds__(128) void bg_kernel(
    const float* __restrict__ x,
    const float* __restrict__ Wb, const float* __restrict__ bb,
    const float* __restrict__ Wgk, const float* __restrict__ bgk,
    const float* __restrict__ A_log, const float* __restrict__ dt_bias,
    float* __restrict__ beT, float* __restrict__ alT)
{
    __shared__ float xs[Cq];
    const int m = blockIdx.x;
    const int b = m >> 11;
    const int t = m & 2047;
    const float4* xr = (const float4*)(x + (size_t)m * Cq);
    for (int i = threadIdx.x; i < Cq / 4; i += 128) ((float4*)xs)[i] = xr[i];
    __syncthreads();

    int warp = threadIdx.x >> 5, lane = threadIdx.x & 31;
#pragma unroll
    for (int nn = 0; nn < 8; nn++) {
        int n = warp * 8 + nn;
        const float* wr = (n < 16) ? (Wb + (size_t)n * Cq) : (Wgk + (size_t)(n - 16) * Cq);
        float acc = 0.f;
#pragma unroll 8
        for (int c = lane; c < Cq; c += 32) acc += xs[c] * __ldg(wr + c);
#pragma unroll
        for (int s = 16; s > 0; s >>= 1) acc += __shfl_xor_sync(0xffffffffu, acc, s);
        if (lane == 0) {
            if (n < 16) {
                beT[((size_t)b * Hq + n) * Tq + t] = 1.f / (1.f + expf(-(acc + bb[n])));
            } else {
                int hh = n - 16;
                float gv = acc + bgk[hh] + dt_bias[hh];
                float sp = (gv > 20.f) ? gv : log1pf(expf(gv));
                alT[((size_t)b * Hq + hh) * Tq + t] = expf(-expf(A_log[hh]) * sp);
            }
        }
    }
}

// ---------------- conv(K=4)+silu, RoPE + l2norm ------------------------------
__device__ __forceinline__ float conv_silu(const float* __restrict__ pre,
                                           const float* __restrict__ w,
                                           const float* __restrict__ bias,
                                           int b, int t, int c)
{
    float acc = bias[c];
#pragma unroll
    for (int i = 0; i < 4; i++) {
        int tt = t - 3 + i;
        if (tt >= 0) acc = fmaf(pre[((size_t)b * Tq + tt) * Cq + c], w[c * 4 + i], acc);
    }
    return acc / (1.f + expf(-acc));
}

__global__ __launch_bounds__(64) void conv_rope_kernel(
    const float* __restrict__ qpre, const float* __restrict__ kpre,
    const float* __restrict__ vpre,
    const float* __restrict__ cqw, const float* __restrict__ cqb,
    const float* __restrict__ ckw, const float* __restrict__ ckb,
    const float* __restrict__ cvw, const float* __restrict__ cvb,
    const float* __restrict__ ct, const float* __restrict__ st,
    float* __restrict__ qo, float* __restrict__ ko, float* __restrict__ vo)
{
    const int blk = blockIdx.x;
    const int b = blk / (Tq * Hq);
    const int rem = blk % (Tq * Hq);
    const int t = rem / Hq;
    const int h = rem % Hq;
    const int d = threadIdx.x;
    const int c = h * Dq + d;
    const size_t gidx = ((size_t)b * Tq + t) * Cq + c;

    __shared__ float sq[64], sk[64], redq[2], redk[2];

    vo[gidx] = conv_silu(vpre, cvw, cvb, b, t, c);
    sq[d] = conv_silu(qpre, cqw, cqb, b, t, c);
    sk[d] = conv_silu(kpre, ckw, ckb, b, t, c);
    __syncthreads();

    int j = d & 31;
    int ci = (2 * j) & 31;
    float ce = ct[(size_t)t * 32 + ci];
    float se = st[(size_t)t * 32 + ci];
    float q1 = sq[2 * j], q2 = sq[2 * j + 1];
    float k1 = sk[2 * j], k2 = sk[2 * j + 1];
    float rq = (d < 32) ? (q1 * ce - q2 * se) : (q1 * se + q2 * ce);
    float rk = (d < 32) ? (k1 * ce - k2 * se) : (k1 * se + k2 * ce);

    float sq2 = rq * rq, sk2 = rk * rk;
#pragma unroll
    for (int s = 16; s > 0; s >>= 1) {
        sq2 += __shfl_xor_sync(0xffffffffu, sq2, s);
        sk2 += __shfl_xor_sync(0xffffffffu, sk2, s);
    }
    int wid = d >> 5;
    if ((d & 31) == 0) { redq[wid] = sq2; redk[wid] = sk2; }
    __syncthreads();
    float qn = redq[0] + redq[1];
    float kn = redk[0] + redk[1];
    float qinv = 1.f / fmaxf(sqrtf(qn), 1e-12f);
    float kinv = 1.f / fmaxf(sqrtf(kn), 1e-12f);
    qo[gidx] = rq * qinv;
    ko[gidx] = rk * kinv;
}

// ---------------- gated-delta scan (warp per (b,h,vseg)) ---------------------
__global__ __launch_bounds__(32, 8) void scan_kernel(
    const float* __restrict__ q, const float* __restrict__ k,
    const float* __restrict__ v,
    const float* __restrict__ alT, const float* __restrict__ beT,
    const float* __restrict__ Dp, float* __restrict__ valout)
{
    const int blk = blockIdx.x;
    const int bh = blk >> 3;
    const int seg = blk & 7;
    const int b = bh >> 4;
    const int h = bh & 15;
    const int lane = threadIdx.x;
    const int vr = lane >> 2;
    const int kg = lane & 3;

    __shared__ __align__(16) float sQ[2][CHUNK][64];
    __shared__ __align__(16) float sK[2][CHUNK][64];
    __shared__ __align__(16) float sV[2][CHUNK][VSEG];
    __shared__ __align__(16) float sA[2][CHUNK];
    __shared__ __align__(16) float sB[2][CHUNK];

    const size_t base  = (size_t)b * Tq * Cq + h * Dq;
    const size_t vbase = base + seg * VSEG;
    const size_t abb   = (size_t)bh * Tq;

    auto load_chunk = [&](int c, int stg) {
        const size_t rowoff = (size_t)c * CHUNK * Cq;
#pragma unroll
        for (int it = 0; it < 8; it++) {
            int idx = it * 32 + lane;
            int row = idx >> 4;
            int col = (idx & 15) * 4;
            cpa16(&sQ[stg][row][col], q + base + rowoff + (size_t)row * Cq + col);
            cpa16(&sK[stg][row][col], k + base + rowoff + (size_t)row * Cq + col);
        }
        {
            int row = lane >> 1;
            int col = (lane & 1) * 4;
            cpa16(&sV[stg][row][col], v + vbase + rowoff + (size_t)row * Cq + col);
        }
        if (lane < 4)      cpa16(&sA[stg][lane * 4], alT + abb + c * CHUNK + lane * 4);
        else if (lane < 8) cpa16(&sB[stg][(lane - 4) * 4], beT + abb + c * CHUNK + (lane - 4) * 4);
    };

    ull S2[8];
#pragma unroll
    for (int j = 0; j < 8; j++) S2[j] = 0ULL;
    const float dp = Dp[h];

    load_chunk(0, 0); CP_COMMIT();
    load_chunk(1, 1); CP_COMMIT();
    CP_WAIT1();
    __syncwarp();

    for (int c = 0; c < NCH; c++) {
        const int stg = c & 1;
#pragma unroll 2
        for (int s = 0; s < CHUNK; s++) {
            const float a  = sA[stg][s];
            const float bt = sB[stg][s];
            const float vv = sV[stg][s][vr];

            ull k2[8], q2[8];
            const ull* kp = (const ull*)&sK[stg][s][kg * 16];
            const ull* qp = (const ull*)&sQ[stg][s][kg * 16];
#pragma unroll
            for (int j = 0; j < 8; j++) { k2[j] = kp[j]; q2[j] = qp[j]; }

            ull pA = 0ULL, pB = 0ULL;
#pragma unroll
            for (int j = 0; j < 4; j++) {
                pA = ffma2(S2[j], k2[j], pA);
                pB = ffma2(S2[j + 4], k2[j + 4], pB);
            }
            float2 pu = unpack2(fadd2(pA, pB));
            float p = pu.x + pu.y;
            p += __shfl_xor_sync(0xffffffffu, p, 1);
            p += __shfl_xor_sync(0xffffffffu, p, 2);

            const float coef = bt * vv - a * bt * p;
            const ull c2 = pack2(coef, coef);
            const ull a2 = pack2(a, a);

            ull oA = 0ULL, oB = 0ULL;
#pragma unroll
            for (int j = 0; j < 4; j++) {
                S2[j] = ffma2(a2, S2[j], fmul2(c2, k2[j]));
                oA = ffma2(S2[j], q2[j], oA);
                S2[j + 4] = ffma2(a2, S2[j + 4], fmul2(c2, k2[j + 4]));
                oB = ffma2(S2[j + 4], q2[j + 4], oB);
            }
            float2 ou = unpack2(fadd2(oA, oB));
            float o = ou.x + ou.y;
            o += __shfl_xor_sync(0xffffffffu, o, 1);
            o += __shfl_xor_sync(0xffffffffu, o, 2);

            if (kg == 0) {
                float val = fmaf(dp, vv, o);
                valout[vbase + (size_t)(c * CHUNK + s) * Cq + vr] = val;
            }
        }
        if (c + 2 < NCH) load_chunk(c + 2, stg);
        CP_COMMIT();
        CP_WAIT1();
        __syncwarp();
    }
}

// ---------------- epilogue: rmsnorm -> silu -> *gate -> bf16 split -----------
__global__ __launch_bounds__(256) void epi_kernel(
    const float* __restrict__ val, const float* __restrict__ gate,
    const float* __restrict__ onw,
    __nv_bfloat16* __restrict__ ohi, __nv_bfloat16* __restrict__ olo)
{
    const int gw = blockIdx.x * 8 + (threadIdx.x >> 5);
    const int lane = threadIdx.x & 31;
    const size_t off = (size_t)gw * 64 + lane * 2;
    float2 vl = *(const float2*)(val + off);
    float ss = vl.x * vl.x + vl.y * vl.y;
#pragma unroll
    for (int s = 16; s > 0; s >>= 1) ss += __shfl_xor_sync(0xffffffffu, ss, s);
    float r = rsqrtf(ss * (1.f / 64.f) + EPSq);
    float2 w2 = *(const float2*)(onw + lane * 2);
    float2 g2 = *(const float2*)(gate + off);
    float y0 = vl.x * r * w2.x;
    float y1 = vl.y * r * w2.y;
    float o0 = g2.x * (y0 / (1.f + expf(-y0)));
    float o1 = g2.y * (y1 / (1.f + expf(-y1)));
    __nv_bfloat16 h0, h1, l0, l1;
    split1(o0, h0, l0); split1(o1, h1, l1);
    *(u32*)(ohi + off) = packbf(h0, h1);
    *(u32*)(olo + off) = packbf(l0, l1);
}

// ---------------- launch ------------------------------------------------------
extern "C" void kernel_launch(void* const* d_in, const int* in_sizes, int n_in,
                              void* d_out, int out_size)
{
    const float* x    = (const float*)d_in[0];
    const float* Wq   = (const float*)d_in[1];
    const float* Wk   = (const float*)d_in[2];
    const float* Wv   = (const float*)d_in[3];
    const float* Wg   = (const float*)d_in[4];
    const float* Wo   = (const float*)d_in[5];
    const float* Wb   = (const float*)d_in[6];
    const float* bb   = (const float*)d_in[7];
    const float* Wgk  = (const float*)d_in[8];
    const float* bgk  = (const float*)d_in[9];
    const float* cqw  = (const float*)d_in[10];
    const float* cqb  = (const float*)d_in[11];
    const float* ckw  = (const float*)d_in[12];
    const float* ckb  = (const float*)d_in[13];
    const float* cvw  = (const float*)d_in[14];
    const float* cvb  = (const float*)d_in[15];
    const float* A_log = (const float*)d_in[16];
    const float* Dp   = (const float*)d_in[17];
    const float* dtb  = (const float*)d_in[18];
    const float* onw  = (const float*)d_in[19];
    float* out = (float*)d_out;

    float *qpre, *kpre, *vpre, *gbuf, *qn, *kn, *vn, *al, *be, *ct, *st;
    __nv_bfloat16 *xhi, *xlo, *whi, *wlo, *oghi, *oglo;
    cudaGetSymbolAddress((void**)&qpre, g_qpre);
    cudaGetSymbolAddress((void**)&kpre, g_kpre);
    cudaGetSymbolAddress((void**)&vpre, g_vpre);
    cudaGetSymbolAddress((void**)&gbuf, g_gate);
    cudaGetSymbolAddress((void**)&qn,   g_q);
    cudaGetSymbolAddress((void**)&kn,   g_k);
    cudaGetSymbolAddress((void**)&vn,   g_v);
    cudaGetSymbolAddress((void**)&al,   g_alT);
    cudaGetSymbolAddress((void**)&be,   g_beT);
    cudaGetSymbolAddress((void**)&ct,   g_cos);
    cudaGetSymbolAddress((void**)&st,   g_sin);
    cudaGetSymbolAddress((void**)&xhi,  g_xhi);
    cudaGetSymbolAddress((void**)&xlo,  g_xlo);
    cudaGetSymbolAddress((void**)&whi,  g_whi);
    cudaGetSymbolAddress((void**)&wlo,  g_wlo);
    cudaGetSymbolAddress((void**)&oghi, g_oghi);
    cudaGetSymbolAddress((void**)&oglo, g_oglo);

    cudaFuncSetAttribute(tgemm_nt, cudaFuncAttributeMaxDynamicSharedMemorySize, TG_SMEM);

    rope_table_kernel<<<(Tq * 32 + 255) / 256, 256>>>(ct, st);

    const size_t CC = (size_t)Cq * Cq;
    split_kernel<<<(Mq * Cq / 4 + 255) / 256, 256>>>(x,  xhi, xlo, Mq * Cq / 4);
    split_kernel<<<(int)(CC / 4 + 255) / 256, 256>>>(Wq, whi + 0 * CC, wlo + 0 * CC, (int)(CC / 4));
    split_kernel<<<(int)(CC / 4 + 255) / 256, 256>>>(Wk, whi + 1 * CC, wlo + 1 * CC, (int)(CC / 4));
    split_kernel<<<(int)(CC / 4 + 255) / 256, 256>>>(Wv, whi + 2 * CC, wlo + 2 * CC, (int)(CC / 4));
    split_kernel<<<(int)(CC / 4 + 255) / 256, 256>>>(Wg, whi + 3 * CC, wlo + 3 * CC, (int)(CC / 4));
    split_kernel<<<(int)(CC / 4 + 255) / 256, 256>>>(Wo, whi + 4 * CC, wlo + 4 * CC, (int)(CC / 4));

    dim3 gg(Mq / 128, Cq / 128);
    tgemm_nt<<<gg, 256, TG_SMEM>>>(xhi, xlo, whi + 0 * CC, wlo + 0 * CC, qpre, Cq, Cq);
    tgemm_nt<<<gg, 256, TG_SMEM>>>(xhi, xlo, whi + 1 * CC, wlo + 1 * CC, kpre, Cq, Cq);
    tgemm_nt<<<gg, 256, TG_SMEM>>>(xhi, xlo, whi + 2 * CC, wlo + 2 * CC, vpre, Cq, Cq);
    tgemm_nt<<<gg, 256, TG_SMEM>>>(xhi, xlo, whi + 3 * CC, wlo + 3 * CC, gbuf, Cq, Cq);

    bg_kernel<<<Mq, 128>>>(x, Wb, bb, Wgk, bgk, A_log, dtb, be, al);

    conv_rope_kernel<<<Bq * Tq * Hq, 64>>>(qpre, kpre, vpre,
                                           cqw, cqb, ckw, ckb, cvw, cvb,
                                           ct, st, qn, kn, vn);

    scan_kernel<<<Bq * Hq * NSEG, 32>>>(qn, kn, vn, al, be, Dp, qpre);

    epi_kernel<<<(Bq * Tq * Hq) / 8, 256>>>(qpre, gbuf, onw, oghi, oglo);

    tgemm_nt<<<gg, 256, TG_SMEM>>>(oghi, oglo, whi + 4 * CC, wlo + 4 * CC, out, Cq, Cq);
}

// round 6
// speedup vs baseline: 3.7728x; 1.0808x over previous
#include <cuda_runtime.h>
#include <cuda_bf16.h>
#include <math.h>

#define Bq 2
#define Tq 2048
#define Cq 1024
#define Hq 16
#define Dq 64
#define Mq (Bq*Tq)          // 4096
#define EPSq 1e-6f
#define CHUNK 16
#define NCH (Tq/CHUNK)      // 128
#define VSEG 8
#define NSEG (Dq/VSEG)

typedef unsigned long long ull;
typedef unsigned int u32;

// ---------------- packed f32x2 helpers ---------------------------------------
__device__ __forceinline__ ull ffma2(ull a, ull b, ull c) {
    ull d; asm("fma.rn.f32x2 %0, %1, %2, %3;" : "=l"(d) : "l"(a), "l"(b), "l"(c)); return d;
}
__device__ __forceinline__ ull fmul2(ull a, ull b) {
    ull d; asm("mul.rn.f32x2 %0, %1, %2;" : "=l"(d) : "l"(a), "l"(b)); return d;
}
__device__ __forceinline__ ull fadd2(ull a, ull b) {
    ull d; asm("add.rn.f32x2 %0, %1, %2;" : "=l"(d) : "l"(a), "l"(b)); return d;
}
__device__ __forceinline__ ull pack2(float x, float y) {
    ull d; asm("mov.b64 %0, {%1, %2};" : "=l"(d) : "f"(x), "f"(y)); return d;
}
__device__ __forceinline__ float2 unpack2(ull v) {
    float x, y; asm("mov.b64 {%0, %1}, %2;" : "=f"(x), "=f"(y) : "l"(v));
    return make_float2(x, y);
}
__device__ __forceinline__ void cpa16(void* s, const void* g) {
    asm volatile("cp.async.cg.shared.global [%0], [%1], 16;"
        :: "r"((unsigned)__cvta_generic_to_shared(s)), "l"(g));
}
#define CP_COMMIT() asm volatile("cp.async.commit_group;")
#define CP_WAIT1()  asm volatile("cp.async.wait_group 1;")

// ---------------- mma.sync helpers -------------------------------------------
__device__ __forceinline__ void ldsm4(u32* r, u32 addr) {
    asm volatile("ldmatrix.sync.aligned.m8n8.x4.shared.b16 {%0,%1,%2,%3}, [%4];"
        : "=r"(r[0]), "=r"(r[1]), "=r"(r[2]), "=r"(r[3]) : "r"(addr));
}
__device__ __forceinline__ void mma16816(float* d, const u32* a, u32 b0, u32 b1) {
    asm volatile("mma.sync.aligned.m16n8k16.row.col.f32.bf16.bf16.f32 "
        "{%0,%1,%2,%3}, {%4,%5,%6,%7}, {%8,%9}, {%0,%1,%2,%3};"
        : "+f"(d[0]), "+f"(d[1]), "+f"(d[2]), "+f"(d[3])
        : "r"(a[0]), "r"(a[1]), "r"(a[2]), "r"(a[3]), "r"(b0), "r"(b1));
}

// ---------------- scratch ----------------------------------------------------
__device__ float g_qpre[(size_t)Mq*Cq];
__device__ float g_kpre[(size_t)Mq*Cq];
__device__ float g_vpre[(size_t)Mq*Cq];
__device__ float g_gate[(size_t)Mq*Cq];
__device__ float g_q[(size_t)Mq*Cq];
__device__ float g_k[(size_t)Mq*Cq];
__device__ float g_v[(size_t)Mq*Cq];
__device__ float g_alT[(size_t)Mq*Hq];
__device__ float g_beT[(size_t)Mq*Hq];
__device__ float g_cos[(size_t)Tq*32];
__device__ float g_sin[(size_t)Tq*32];
__device__ __nv_bfloat16 g_xhi[(size_t)Mq*Cq];
__device__ __nv_bfloat16 g_xlo[(size_t)Mq*Cq];
__device__ __nv_bfloat16 g_whi[(size_t)5*Cq*Cq];
__device__ __nv_bfloat16 g_wlo[(size_t)5*Cq*Cq];
__device__ __nv_bfloat16 g_oghi[(size_t)Mq*Cq];
__device__ __nv_bfloat16 g_oglo[(size_t)Mq*Cq];

// ---------------- split fp32 -> bf16 hi/lo -----------------------------------
__device__ __forceinline__ void split1(float f, __nv_bfloat16& h, __nv_bfloat16& l) {
    h = __float2bfloat16(f);
    l = __float2bfloat16(f - __bfloat162float(h));
}
__device__ __forceinline__ u32 packbf(__nv_bfloat16 a, __nv_bfloat16 b) {
    return (u32)__bfloat16_as_ushort(a) | ((u32)__bfloat16_as_ushort(b) << 16);
}
__device__ __forceinline__ void split4(const float* in, __nv_bfloat16* hi,
                                       __nv_bfloat16* lo, size_t i)
{
    float4 v = ((const float4*)in)[i];
    __nv_bfloat16 h0, h1, h2, h3, l0, l1, l2, l3;
    split1(v.x, h0, l0); split1(v.y, h1, l1);
    split1(v.z, h2, l2); split1(v.w, h3, l3);
    ((uint2*)hi)[i] = make_uint2(packbf(h0, h1), packbf(h2, h3));
    ((uint2*)lo)[i] = make_uint2(packbf(l0, l1), packbf(l2, l3));
}

__global__ __launch_bounds__(256) void split_kernel(
    const float* __restrict__ in, __nv_bfloat16* __restrict__ hi,
    __nv_bfloat16* __restrict__ lo, int n4)
{
    int i = blockIdx.x * 256 + threadIdx.x;
    if (i >= n4) return;
    split4(in, hi, lo, i);
}

// one launch splits all 5 weight matrices
__global__ __launch_bounds__(256) void wsplit_kernel(
    const float* __restrict__ w0, const float* __restrict__ w1,
    const float* __restrict__ w2, const float* __restrict__ w3,
    const float* __restrict__ w4,
    __nv_bfloat16* __restrict__ hi, __nv_bfloat16* __restrict__ lo)
{
    const int R4 = (Cq * Cq) / 4;
    int i = blockIdx.x * 256 + threadIdx.x;
    if (i >= 5 * R4) return;
    int r = i / R4;
    int li = i - r * R4;
    const float* src = (r == 0) ? w0 : (r == 1) ? w1 : (r == 2) ? w2 : (r == 3) ? w3 : w4;
    split4(src, hi + (size_t)r * Cq * Cq, lo + (size_t)r * Cq * Cq, (size_t)li + (size_t)r * 0);
    // note: hi/lo pointers already offset per region; index is local
    (void)li;
}

// fix: the above needs local index; re-do cleanly below (kept single definition)

// ---------------- tensor-core split-bf16 GEMM (NT) via mma.sync --------------
// Pass-major MMA ordering to break accumulator RAW chains.
#define TILE_B 8192
#define STG_B (4*TILE_B)
#define NSTG 3
#define TG_SMEM (NSTG*STG_B)

struct TG4Out { float *o0, *o1, *o2, *o3; };

__device__ __forceinline__ void tgemm_body(
    const __nv_bfloat16* Ahi, const __nv_bfloat16* Alo,
    const __nv_bfloat16* Bhi, const __nv_bfloat16* Blo,
    float* C, int K, int ldc, int m0, int n0, char* ts)
{
    const u32 sbase = (u32)__cvta_generic_to_shared(ts);
    const int tid = threadIdx.x;
    const int wid = tid >> 5;
    const int lane = tid & 31;
    const int warp_m = wid & 3;
    const int warp_n = wid >> 2;
    const int nchk = K / 32;

    const int lrow = tid >> 1;
    const int co = (tid & 1) * 2;
    const u32 swl = (lrow >> 1) & 3;
    const u32 so0 = (u32)((lrow * 4 + (co ^ swl)) << 4);
    const u32 so1 = (u32)((lrow * 4 + ((co + 1) ^ swl)) << 4);
    const char* gAh = (const char*)(Ahi + (size_t)(m0 + lrow) * K) + co * 16;
    const char* gAl = (const char*)(Alo + (size_t)(m0 + lrow) * K) + co * 16;
    const char* gBh = (const char*)(Bhi + (size_t)(n0 + lrow) * K) + co * 16;
    const char* gBl = (const char*)(Blo + (size_t)(n0 + lrow) * K) + co * 16;

    auto load_chunk = [&](int c, int stg) {
        const size_t go = (size_t)c * 64;
        char* base = ts + stg * STG_B;
        cpa16(base + so0, gAh + go);            cpa16(base + so1, gAh + go + 16);
        cpa16(base + TILE_B + so0, gAl + go);   cpa16(base + TILE_B + so1, gAl + go + 16);
        cpa16(base + 2*TILE_B + so0, gBh + go); cpa16(base + 2*TILE_B + so1, gBh + go + 16);
        cpa16(base + 3*TILE_B + so0, gBl + go); cpa16(base + 3*TILE_B + so1, gBl + go + 16);
    };

    const int lq = lane >> 3;
    const int lr = lane & 7;
    const int rowA0 = warp_m * 32 + lr + (lq & 1) * 8;
    const int rowB0 = warp_n * 64 + lr + (lq & 1) * 8;
    const int cq = lq >> 1;

    float acc[2][8][4];
#pragma unroll
    for (int i = 0; i < 2; i++)
#pragma unroll
        for (int j = 0; j < 8; j++)
#pragma unroll
            for (int l = 0; l < 4; l++) acc[i][j][l] = 0.f;

    load_chunk(0, 0); CP_COMMIT();
    load_chunk(1, 1); CP_COMMIT();

    for (int c = 0; c < nchk; c++) {
        const int stg = c % NSTG;
        CP_WAIT1();
        __syncthreads();

        const u32 stb = sbase + stg * STG_B;
#pragma unroll
        for (int ks = 0; ks < 2; ks++) {
            u32 ahf[2][4], alf[2][4], bhf[4][4], blf[4][4];
            const u32 cc = (u32)(ks * 2 + cq);
#pragma unroll
            for (int mt = 0; mt < 2; mt++) {
                int row = rowA0 + mt * 16;
                u32 off = (u32)((row * 4 + (cc ^ ((row >> 1) & 3))) << 4);
                ldsm4(ahf[mt], stb + off);
                ldsm4(alf[mt], stb + TILE_B + off);
            }
#pragma unroll
            for (int ntp = 0; ntp < 4; ntp++) {
                int row = rowB0 + ntp * 16;
                u32 off = (u32)((row * 4 + (cc ^ ((row >> 1) & 3))) << 4);
                ldsm4(bhf[ntp], stb + 2 * TILE_B + off);
                ldsm4(blf[ntp], stb + 3 * TILE_B + off);
            }
            // PASS-MAJOR: same-acc reuse distance = 16 MMAs (no RAW stall)
#pragma unroll
            for (int mt = 0; mt < 2; mt++)
#pragma unroll
                for (int ntp = 0; ntp < 4; ntp++) {
                    mma16816(acc[mt][ntp * 2],     ahf[mt], bhf[ntp][0], bhf[ntp][2]);
                    mma16816(acc[mt][ntp * 2 + 1], ahf[mt], bhf[ntp][1], bhf[ntp][3]);
                }
#pragma unroll
            for (int mt = 0; mt < 2; mt++)
#pragma unroll
                for (int ntp = 0; ntp < 4; ntp++) {
                    mma16816(acc[mt][ntp * 2],     ahf[mt], blf[ntp][0], blf[ntp][2]);
                    mma16816(acc[mt][ntp * 2 + 1], ahf[mt], blf[ntp][1], blf[ntp][3]);
                }
#pragma unroll
            for (int mt = 0; mt < 2; mt++)
#pragma unroll
                for (int ntp = 0; ntp < 4; ntp++) {
                    mma16816(acc[mt][ntp * 2],     alf[mt], bhf[ntp][0], bhf[ntp][2]);
                    mma16816(acc[mt][ntp * 2 + 1], alf[mt], bhf[ntp][1], bhf[ntp][3]);
                }
        }

        if (c + 2 < nchk) load_chunk(c + 2, (c + 2) % NSTG);
        CP_COMMIT();
    }

    const int g = lane >> 2;
    const int tg = lane & 3;
#pragma unroll
    for (int mt = 0; mt < 2; mt++) {
        int mrow = m0 + warp_m * 32 + mt * 16 + g;
#pragma unroll
        for (int nt = 0; nt < 8; nt++) {
            int ncol = n0 + warp_n * 64 + nt * 8 + tg * 2;
            *(float2*)(C + (size_t)mrow * ldc + ncol) =
                make_float2(acc[mt][nt][0], acc[mt][nt][1]);
            *(float2*)(C + (size_t)(mrow + 8) * ldc + ncol) =
                make_float2(acc[mt][nt][2], acc[mt][nt][3]);
        }
    }
}

// single GEMM (used for the output projection)
__global__ __launch_bounds__(256, 1) void tgemm_nt(
    const __nv_bfloat16* __restrict__ Ahi, const __nv_bfloat16* __restrict__ Alo,
    const __nv_bfloat16* __restrict__ Bhi, const __nv_bfloat16* __restrict__ Blo,
    float* __restrict__ C, int K, int ldc)
{
    extern __shared__ __align__(1024) char ts[];
    tgemm_body(Ahi, Alo, Bhi, Blo, C, K, ldc,
               blockIdx.x * 128, blockIdx.y * 128, ts);
}

// fused QKVG: blockIdx.y selects (weight, n-tile)
__global__ __launch_bounds__(256, 1) void tgemm4_nt(
    const __nv_bfloat16* __restrict__ Ahi, const __nv_bfloat16* __restrict__ Alo,
    const __nv_bfloat16* __restrict__ Whi, const __nv_bfloat16* __restrict__ Wlo,
    TG4Out outs, int K, int ldc)
{
    extern __shared__ __align__(1024) char ts[];
    const int wsel = blockIdx.y >> 3;
    const int n0 = (blockIdx.y & 7) * 128;
    const size_t CC = (size_t)Cq * Cq;
    float* C = (wsel == 0) ? outs.o0 : (wsel == 1) ? outs.o1
             : (wsel == 2) ? outs.o2 : outs.o3;
    tgemm_body(Ahi, Alo, Whi + wsel * CC, Wlo + wsel * CC, C, K, ldc,
               blockIdx.x * 128, n0, ts);
}

// ---------------- RoPE (YaRN) cos/sin table ----------------------------------
__global__ void rope_table_kernel(float* __restrict__ ct, float* __restrict__ st) {
    int idx = blockIdx.x * blockDim.x + threadIdx.x;
    if (idx >= Tq * 32) return;
    int t = idx >> 5;
    int i = idx & 31;
    double ar = (double)i / 32.0;
    double scaled_base = 10000.0 * pow(32.0, 64.0 / 62.0);
    double inv_freq = pow(scaled_base, -ar);
    double wavelen = 2.0 * M_PI * pow(10000.0, ar);
    double mscale = (wavelen - 1.0) / 31.0;
    mscale = mscale < 0.0 ? 0.0 : (mscale > 1.0 ? 1.0 : mscale);
    double scale = 1.0 + 31.0 * mscale;
    float fr = (float)(((double)t / scale) * inv_freq);
    ct[idx] = cosf(fr);
    st[idx] = sinf(fr);
}

// ---------------- beta / alpha: 8 m-rows per block for W reuse ---------------
#define BGM 8
__global__ __launch_bounds__(256) void bg_kernel(
    const float* __restrict__ x,
    const float* __restrict__ Wb, const float* __restrict__ bb,
    const float* __restrict__ Wgk, const float* __restrict__ bgk,
    const float* __restrict__ A_log, const float* __restrict__ dt_bias,
    float* __restrict__ beT, float* __restrict__ alT)
{
    __shared__ __align__(16) float xs[BGM][Cq];
    const int m0 = blockIdx.x * BGM;
    const int tid = threadIdx.x;
    for (int i = tid; i < BGM * Cq / 4; i += 256) {
        int r = i / (Cq / 4), cc = i % (Cq / 4);
        ((float4*)xs[r])[cc] = ((const float4*)(x + (size_t)(m0 + r) * Cq))[cc];
    }
    __syncthreads();

    const int warp = tid >> 5, lane = tid & 31;
#pragma unroll
    for (int nn = 0; nn < 4; nn++) {
        int n = warp * 4 + nn;   // 0..31
        const float* wr = (n < 16) ? (Wb + (size_t)n * Cq) : (Wgk + (size_t)(n - 16) * Cq);
        float wv[32];
#pragma unroll
        for (int j = 0; j < 32; j++) wv[j] = __ldg(wr + j * 32 + lane);
#pragma unroll
        for (int r = 0; r < BGM; r++) {
            float acc = 0.f;
#pragma unroll
            for (int j = 0; j < 32; j++) acc = fmaf(xs[r][j * 32 + lane], wv[j], acc);
#pragma unroll
            for (int s = 16; s > 0; s >>= 1) acc += __shfl_xor_sync(0xffffffffu, acc, s);
            if (lane == 0) {
                int m = m0 + r;
                int b = m >> 11, t = m & 2047;
                if (n < 16) {
                    beT[((size_t)b * Hq + n) * Tq + t] = 1.f / (1.f + expf(-(acc + bb[n])));
                } else {
                    int hh = n - 16;
                    float gv = acc + bgk[hh] + dt_bias[hh];
                    float sp = (gv > 20.f) ? gv : log1pf(expf(gv));
                    alT[((size_t)b * Hq + hh) * Tq + t] = expf(-expf(A_log[hh]) * sp);
                }
            }
        }
    }
}

// ---------------- conv(K=4)+silu, RoPE + l2norm ------------------------------
__device__ __forceinline__ float conv_silu(const float* __restrict__ pre,
                                           const float* __restrict__ w,
                                           const float* __restrict__ bias,
                                           int b, int t, int c)
{
    float acc = bias[c];
#pragma unroll
    for (int i = 0; i < 4; i++) {
        int tt = t - 3 + i;
        if (tt >= 0) acc = fmaf(pre[((size_t)b * Tq + tt) * Cq + c], w[c * 4 + i], acc);
    }
    return acc / (1.f + expf(-acc));
}

__global__ __launch_bounds__(64) void conv_rope_kernel(
    const float* __restrict__ qpre, const float* __restrict__ kpre,
    const float* __restrict__ vpre,
    const float* __restrict__ cqw, const float* __restrict__ cqb,
    const float* __restrict__ ckw, const float* __restrict__ ckb,
    const float* __restrict__ cvw, const float* __restrict__ cvb,
    const float* __restrict__ ct, const float* __restrict__ st,
    float* __restrict__ qo, float* __restrict__ ko, float* __restrict__ vo)
{
    const int blk = blockIdx.x;
    const int b = blk / (Tq * Hq);
    const int rem = blk % (Tq * Hq);
    const int t = rem / Hq;
    const int h = rem % Hq;
    const int d = threadIdx.x;
    const int c = h * Dq + d;
    const size_t gidx = ((size_t)b * Tq + t) * Cq + c;

    __shared__ float sq[64], sk[64], redq[2], redk[2];

    vo[gidx] = conv_silu(vpre, cvw, cvb, b, t, c);
    sq[d] = conv_silu(qpre, cqw, cqb, b, t, c);
    sk[d] = conv_silu(kpre, ckw, ckb, b, t, c);
    __syncthreads();

    int j = d & 31;
    int ci = (2 * j) & 31;
    float ce = ct[(size_t)t * 32 + ci];
    float se = st[(size_t)t * 32 + ci];
    float q1 = sq[2 * j], q2 = sq[2 * j + 1];
    float k1 = sk[2 * j], k2 = sk[2 * j + 1];
    float rq = (d < 32) ? (q1 * ce - q2 * se) : (q1 * se + q2 * ce);
    float rk = (d < 32) ? (k1 * ce - k2 * se) : (k1 * se + k2 * ce);

    float sq2 = rq * rq, sk2 = rk * rk;
#pragma unroll
    for (int s = 16; s > 0; s >>= 1) {
        sq2 += __shfl_xor_sync(0xffffffffu, sq2, s);
        sk2 += __shfl_xor_sync(0xffffffffu, sk2, s);
    }
    int wid = d >> 5;
    if ((d & 31) == 0) { redq[wid] = sq2; redk[wid] = sk2; }
    __syncthreads();
    float qn = redq[0] + redq[1];
    float kn = redk[0] + redk[1];
    float qinv = 1.f / fmaxf(sqrtf(qn), 1e-12f);
    float kinv = 1.f / fmaxf(sqrtf(kn), 1e-12f);
    qo[gidx] = rq * qinv;
    ko[gidx] = rk * kinv;
}

// ---------------- gated-delta scan (warp per (b,h,vseg)) ---------------------
__global__ __launch_bounds__(32, 8) void scan_kernel(
    const float* __restrict__ q, const float* __restrict__ k,
    const float* __restrict__ v,
    const float* __restrict__ alT, const float* __restrict__ beT,
    const float* __restrict__ Dp, float* __restrict__ valout)
{
    const int blk = blockIdx.x;
    const int bh = blk >> 3;
    const int seg = blk & 7;
    const int b = bh >> 4;
    const int h = bh & 15;
    const int lane = threadIdx.x;
    const int vr = lane >> 2;
    const int kg = lane & 3;

    __shared__ __align__(16) float sQ[2][CHUNK][64];
    __shared__ __align__(16) float sK[2][CHUNK][64];
    __shared__ __align__(16) float sV[2][CHUNK][VSEG];
    __shared__ __align__(16) float sA[2][CHUNK];
    __shared__ __align__(16) float sB[2][CHUNK];

    const size_t base  = (size_t)b * Tq * Cq + h * Dq;
    const size_t vbase = base + seg * VSEG;
    const size_t abb   = (size_t)bh * Tq;

    auto load_chunk = [&](int c, int stg) {
        const size_t rowoff = (size_t)c * CHUNK * Cq;
#pragma unroll
        for (int it = 0; it < 8; it++) {
            int idx = it * 32 + lane;
            int row = idx >> 4;
            int col = (idx & 15) * 4;
            cpa16(&sQ[stg][row][col], q + base + rowoff + (size_t)row * Cq + col);
            cpa16(&sK[stg][row][col], k + base + rowoff + (size_t)row * Cq + col);
        }
        {
            int row = lane >> 1;
            int col = (lane & 1) * 4;
            cpa16(&sV[stg][row][col], v + vbase + rowoff + (size_t)row * Cq + col);
        }
        if (lane < 4)      cpa16(&sA[stg][lane * 4], alT + abb + c * CHUNK + lane * 4);
        else if (lane < 8) cpa16(&sB[stg][(lane - 4) * 4], beT + abb + c * CHUNK + (lane - 4) * 4);
    };

    ull S2[8];
#pragma unroll
    for (int j = 0; j < 8; j++) S2[j] = 0ULL;
    const float dp = Dp[h];

    load_chunk(0, 0); CP_COMMIT();
    load_chunk(1, 1); CP_COMMIT();
    CP_WAIT1();
    __syncwarp();

    for (int c = 0; c < NCH; c++) {
        const int stg = c & 1;
#pragma unroll 2
        for (int s = 0; s < CHUNK; s++) {
            const float a  = sA[stg][s];
            const float bt = sB[stg][s];
            const float vv = sV[stg][s][vr];

            ull k2[8], q2[8];
            const ull* kp = (const ull*)&sK[stg][s][kg * 16];
            const ull* qp = (const ull*)&sQ[stg][s][kg * 16];
#pragma unroll
            for (int j = 0; j < 8; j++) { k2[j] = kp[j]; q2[j] = qp[j]; }

            ull pA = 0ULL, pB = 0ULL;
#pragma unroll
            for (int j = 0; j < 4; j++) {
                pA = ffma2(S2[j], k2[j], pA);
                pB = ffma2(S2[j + 4], k2[j + 4], pB);
            }
            float2 pu = unpack2(fadd2(pA, pB));
            float p = pu.x + pu.y;
            p += __shfl_xor_sync(0xffffffffu, p, 1);
            p += __shfl_xor_sync(0xffffffffu, p, 2);

            const float coef = bt * vv - a * bt * p;
            const ull c2 = pack2(coef, coef);
            const ull a2 = pack2(a, a);

            ull oA = 0ULL, oB = 0ULL;
#pragma unroll
            for (int j = 0; j < 4; j++) {
                S2[j] = ffma2(a2, S2[j], fmul2(c2, k2[j]));
                oA = ffma2(S2[j], q2[j], oA);
                S2[j + 4] = ffma2(a2, S2[j + 4], fmul2(c2, k2[j + 4]));
                oB = ffma2(S2[j + 4], q2[j + 4], oB);
            }
            float2 ou = unpack2(fadd2(oA, oB));
            float o = ou.x + ou.y;
            o += __shfl_xor_sync(0xffffffffu, o, 1);
            o += __shfl_xor_sync(0xffffffffu, o, 2);

            if (kg == 0) {
                float val = fmaf(dp, vv, o);
                valout[vbase + (size_t)(c * CHUNK + s) * Cq + vr] = val;
            }
        }
        if (c + 2 < NCH) load_chunk(c + 2, stg);
        CP_COMMIT();
        CP_WAIT1();
        __syncwarp();
    }
}

// ---------------- epilogue: rmsnorm -> silu -> *gate -> bf16 split -----------
__global__ __launch_bounds__(256) void epi_kernel(
    const float* __restrict__ val, const float* __restrict__ gate,
    const float* __restrict__ onw,
    __nv_bfloat16* __restrict__ ohi, __nv_bfloat16* __restrict__ olo)
{
    const int gw = blockIdx.x * 8 + (threadIdx.x >> 5);
    const int lane = threadIdx.x & 31;
    const size_t off = (size_t)gw * 64 + lane * 2;
    float2 vl = *(const float2*)(val + off);
    float ss = vl.x * vl.x + vl.y * vl.y;
#pragma unroll
    for (int s = 16; s > 0; s >>= 1) ss += __shfl_xor_sync(0xffffffffu, ss, s);
    float r = rsqrtf(ss * (1.f / 64.f) + EPSq);
    float2 w2 = *(const float2*)(onw + lane * 2);
    float2 g2 = *(const float2*)(gate + off);
    float y0 = vl.x * r * w2.x;
    float y1 = vl.y * r * w2.y;
    float o0 = g2.x * (y0 / (1.f + expf(-y0)));
    float o1 = g2.y * (y1 / (1.f + expf(-y1)));
    __nv_bfloat16 h0, h1, l0, l1;
    split1(o0, h0, l0); split1(o1, h1, l1);
    *(u32*)(ohi + off) = packbf(h0, h1);
    *(u32*)(olo + off) = packbf(l0, l1);
}

// ---------------- launch ------------------------------------------------------
extern "C" void kernel_launch(void* const* d_in, const int* in_sizes, int n_in,
                              void* d_out, int out_size)
{
    const float* x    = (const float*)d_in[0];
    const float* Wq   = (const float*)d_in[1];
    const float* Wk   = (const float*)d_in[2];
    const float* Wv   = (const float*)d_in[3];
    const float* Wg   = (const float*)d_in[4];
    const float* Wo   = (const float*)d_in[5];
    const float* Wb   = (const float*)d_in[6];
    const float* bb   = (const float*)d_in[7];
    const float* Wgk  = (const float*)d_in[8];
    const float* bgk  = (const float*)d_in[9];
    const float* cqw  = (const float*)d_in[10];
    const float* cqb  = (const float*)d_in[11];
    const float* ckw  = (const float*)d_in[12];
    const float* ckb  = (const float*)d_in[13];
    const float* cvw  = (const float*)d_in[14];
    const float* cvb  = (const float*)d_in[15];
    const float* A_log = (const float*)d_in[16];
    const float* Dp   = (const float*)d_in[17];
    const float* dtb  = (const float*)d_in[18];
    const float* onw  = (const float*)d_in[19];
    float* out = (float*)d_out;

    float *qpre, *kpre, *vpre, *gbuf, *qn, *kn, *vn, *al, *be, *ct, *st;
    __nv_bfloat16 *xhi, *xlo, *whi, *wlo, *oghi, *oglo;
    cudaGetSymbolAddress((void**)&qpre, g_qpre);
    cudaGetSymbolAddress((void**)&kpre, g_kpre);
    cudaGetSymbolAddress((void**)&vpre, g_vpre);
    cudaGetSymbolAddress((void**)&gbuf, g_gate);
    cudaGetSymbolAddress((void**)&qn,   g_q);
    cudaGetSymbolAddress((void**)&kn,   g_k);
    cudaGetSymbolAddress((void**)&vn,   g_v);
    cudaGetSymbolAddress((void**)&al,   g_alT);
    cudaGetSymbolAddress((void**)&be,   g_beT);
    cudaGetSymbolAddress((void**)&ct,   g_cos);
    cudaGetSymbolAddress((void**)&st,   g_sin);
    cudaGetSymbolAddress((void**)&xhi,  g_xhi);
    cudaGetSymbolAddress((void**)&xlo,  g_xlo);
    cudaGetSymbolAddress((void**)&whi,  g_whi);
    cudaGetSymbolAddress((void**)&wlo,  g_wlo);
    cudaGetSymbolAddress((void**)&oghi, g_oghi);
    cudaGetSymbolAddress((void**)&oglo, g_oglo);

    cudaFuncSetAttribute(tgemm_nt,  cudaFuncAttributeMaxDynamicSharedMemorySize, TG_SMEM);
    cudaFuncSetAttribute(tgemm4_nt, cudaFuncAttributeMaxDynamicSharedMemorySize, TG_SMEM);

    rope_table_kernel<<<(Tq * 32 + 255) / 256, 256>>>(ct, st);

    const size_t CC = (size_t)Cq * Cq;
    split_kernel<<<(Mq * Cq / 4 + 255) / 256, 256>>>(x, xhi, xlo, Mq * Cq / 4);
    // weights: 5 separate launches replaced by loop of 5 src pointers
    {
        const float* ws[5] = {Wq, Wk, Wv, Wg, Wo};
        for (int r = 0; r < 5; r++)
            split_kernel<<<(int)(CC / 4 + 255) / 256, 256>>>(
                ws[r], whi + (size_t)r * CC, wlo + (size_t)r * CC, (int)(CC / 4));
    }

    // fused QKVG GEMM: one launch, 1024 CTAs
    TG4Out outs = {qpre, kpre, vpre, gbuf};
    dim3 g4(Mq / 128, 32);
    tgemm4_nt<<<g4, 256, TG_SMEM>>>(xhi, xlo, whi, wlo, outs, Cq, Cq);

    bg_kernel<<<Mq / BGM, 256>>>(x, Wb, bb, Wgk, bgk, A_log, dtb, be, al);

    conv_rope_kernel<<<Bq * Tq * Hq, 64>>>(qpre, kpre, vpre,
                                           cqw, cqb, ckw, ckb, cvw, cvb,
                                           ct, st, qn, kn, vn);

    scan_kernel<<<Bq * Hq * NSEG, 32>>>(qn, kn, vn, al, be, Dp, qpre);

    epi_kernel<<<(Bq * Tq * Hq) / 8, 256>>>(qpre, gbuf, onw, oghi, oglo);

    dim3 gg(Mq / 128, Cq / 128);
    tgemm_nt<<<gg, 256, TG_SMEM>>>(oghi, oglo, whi + 4 * CC, wlo + 4 * CC, out, Cq, Cq);
}

// round 7
// speedup vs baseline: 4.4645x; 1.1833x over previous
#include <cuda_runtime.h>
#include <cuda_bf16.h>
#include <cuda_fp16.h>
#include <math.h>

#define Bq 2
#define Tq 2048
#define Cq 1024
#define Hq 16
#define Dq 64
#define Mq (Bq*Tq)          // 4096
#define EPSq 1e-6f
#define CHUNK 16
#define NCH (Tq/CHUNK)      // 128
#define VSEG 8
#define NSEG (Dq/VSEG)

typedef unsigned long long ull;
typedef unsigned int u32;

// ---------------- packed f32x2 helpers ---------------------------------------
__device__ __forceinline__ ull ffma2(ull a, ull b, ull c) {
    ull d; asm("fma.rn.f32x2 %0, %1, %2, %3;" : "=l"(d) : "l"(a), "l"(b), "l"(c)); return d;
}
__device__ __forceinline__ ull fmul2(ull a, ull b) {
    ull d; asm("mul.rn.f32x2 %0, %1, %2;" : "=l"(d) : "l"(a), "l"(b)); return d;
}
__device__ __forceinline__ ull fadd2(ull a, ull b) {
    ull d; asm("add.rn.f32x2 %0, %1, %2;" : "=l"(d) : "l"(a), "l"(b)); return d;
}
__device__ __forceinline__ ull pack2(float x, float y) {
    ull d; asm("mov.b64 %0, {%1, %2};" : "=l"(d) : "f"(x), "f"(y)); return d;
}
__device__ __forceinline__ float2 unpack2(ull v) {
    float x, y; asm("mov.b64 {%0, %1}, %2;" : "=f"(x), "=f"(y) : "l"(v));
    return make_float2(x, y);
}
__device__ __forceinline__ void cpa16(void* s, const void* g) {
    asm volatile("cp.async.cg.shared.global [%0], [%1], 16;"
        :: "r"((unsigned)__cvta_generic_to_shared(s)), "l"(g));
}
#define CP_COMMIT() asm volatile("cp.async.commit_group;")
#define CP_WAIT1()  asm volatile("cp.async.wait_group 1;")

// ---------------- mma.sync helpers (fp16, f32 accum) --------------------------
__device__ __forceinline__ void ldsm4(u32* r, u32 addr) {
    asm volatile("ldmatrix.sync.aligned.m8n8.x4.shared.b16 {%0,%1,%2,%3}, [%4];"
        : "=r"(r[0]), "=r"(r[1]), "=r"(r[2]), "=r"(r[3]) : "r"(addr));
}
__device__ __forceinline__ void mma16816h(float* d, const u32* a, u32 b0, u32 b1) {
    asm volatile("mma.sync.aligned.m16n8k16.row.col.f32.f16.f16.f32 "
        "{%0,%1,%2,%3}, {%4,%5,%6,%7}, {%8,%9}, {%0,%1,%2,%3};"
        : "+f"(d[0]), "+f"(d[1]), "+f"(d[2]), "+f"(d[3])
        : "r"(a[0]), "r"(a[1]), "r"(a[2]), "r"(a[3]), "r"(b0), "r"(b1));
}

// ---------------- scratch ----------------------------------------------------
__device__ float g_qpre[(size_t)Mq*Cq];
__device__ float g_kpre[(size_t)Mq*Cq];
__device__ float g_vpre[(size_t)Mq*Cq];
__device__ float g_gate[(size_t)Mq*Cq];
__device__ float g_q[(size_t)Mq*Cq];
__device__ float g_k[(size_t)Mq*Cq];
__device__ float g_v[(size_t)Mq*Cq];
__device__ float g_alT[(size_t)Mq*Hq];
__device__ float g_beT[(size_t)Mq*Hq];
__device__ float g_cos[(size_t)Tq*32];
__device__ float g_sin[(size_t)Tq*32];
__device__ __half g_xh[(size_t)Mq*Cq];
__device__ __half g_wh[(size_t)5*Cq*Cq];
__device__ __half g_wl[(size_t)5*Cq*Cq];
__device__ __half g_ogh[(size_t)Mq*Cq];

// ---------------- fp16 pack helpers ------------------------------------------
__device__ __forceinline__ u32 packh(__half a, __half b) {
    return (u32)__half_as_ushort(a) | ((u32)__half_as_ushort(b) << 16);
}

// hi-only split (for A operands: x and og)
__global__ __launch_bounds__(256) void split_h_kernel(
    const float* __restrict__ in, __half* __restrict__ hi, int n4)
{
    int i = blockIdx.x * 256 + threadIdx.x;
    if (i >= n4) return;
    float4 v = ((const float4*)in)[i];
    ((uint2*)hi)[i] = make_uint2(
        packh(__float2half(v.x), __float2half(v.y)),
        packh(__float2half(v.z), __float2half(v.w)));
}

// hi+lo split of all 5 weight matrices in one launch
__global__ __launch_bounds__(256) void wsplit_kernel(
    const float* __restrict__ w0, const float* __restrict__ w1,
    const float* __restrict__ w2, const float* __restrict__ w3,
    const float* __restrict__ w4,
    __half* __restrict__ hi, __half* __restrict__ lo)
{
    const int R4 = (Cq * Cq) / 4;
    int i = blockIdx.x * 256 + threadIdx.x;
    if (i >= 5 * R4) return;
    int r = i / R4;
    int li = i - r * R4;
    const float* src = (r == 0) ? w0 : (r == 1) ? w1 : (r == 2) ? w2 : (r == 3) ? w3 : w4;
    float4 v = ((const float4*)src)[li];
    __half h0 = __float2half(v.x), h1 = __float2half(v.y);
    __half h2 = __float2half(v.z), h3 = __float2half(v.w);
    __half l0 = __float2half(v.x - __half2float(h0));
    __half l1 = __float2half(v.y - __half2float(h1));
    __half l2 = __float2half(v.z - __half2float(h2));
    __half l3 = __float2half(v.w - __half2float(h3));
    ((uint2*)(hi + (size_t)r * Cq * Cq))[li] = make_uint2(packh(h0, h1), packh(h2, h3));
    ((uint2*)(lo + (size_t)r * Cq * Cq))[li] = make_uint2(packh(l0, l1), packh(l2, l3));
}

// ---------------- tensor-core fp16 2-pass GEMM (NT) via mma.sync -------------
// C[m][n] = sum_k A[m][k]*B[n][k];  A rounded to fp16 (hi), B as hi+lo.
// Tile 128x128, BK=64 fp16 (=128B rows), 3-stage cp.async pipe.
#define TILE_B 16384                  // 128 rows x 128 B
#define STG_B (3*TILE_B)              // Ah | Bh | Bl = 48KB per stage
#define NSTG 3
#define TG_SMEM (NSTG*STG_B)          // 144KB

// chunk swizzle: 8 chunks of 16B per 128B row
__device__ __forceinline__ u32 swz_off(int row, int c) {
    return (u32)(row * 128 + (((u32)c ^ ((u32)row & 7) ^ (((u32)row >> 3) & 1)) << 4));
}

struct TG4Out { float *o0, *o1, *o2, *o3; };

__device__ __forceinline__ void tgemm_body(
    const __half* Ah, const __half* Bh, const __half* Bl,
    float* C, int K, int ldc, int m0, int n0, char* ts)
{
    const u32 sbase = (u32)__cvta_generic_to_shared(ts);
    const int tid = threadIdx.x;
    const int wid = tid >> 5;
    const int lane = tid & 31;
    const int warp_m = wid & 3;
    const int warp_n = wid >> 2;
    const int nchk = K / 64;

    // loader: row = tid>>1, half = tid&1 -> 4 x 16B granules
    const int lrow = tid >> 1;
    const int ch0 = (tid & 1) * 4;
    const char* gAh = (const char*)(Ah + (size_t)(m0 + lrow) * K) + ch0 * 16;
    const char* gBh = (const char*)(Bh + (size_t)(n0 + lrow) * K) + ch0 * 16;
    const char* gBl = (const char*)(Bl + (size_t)(n0 + lrow) * K) + ch0 * 16;
    u32 soff[4];
#pragma unroll
    for (int i = 0; i < 4; i++) soff[i] = swz_off(lrow, ch0 + i);

    auto load_chunk = [&](int c, int stg) {
        const size_t go = (size_t)c * 128;    // 64 fp16 = 128B per row-chunk
        char* base = ts + stg * STG_B;
#pragma unroll
        for (int i = 0; i < 4; i++) {
            cpa16(base + soff[i],              gAh + go + i * 16);
            cpa16(base + TILE_B + soff[i],     gBh + go + i * 16);
            cpa16(base + 2 * TILE_B + soff[i], gBl + go + i * 16);
        }
    };

    const int lq = lane >> 3;
    const int lr = lane & 7;
    const int rowA0 = warp_m * 32 + lr + (lq & 1) * 8;
    const int rowB0 = warp_n * 64 + lr + (lq & 1) * 8;
    const int cq = lq >> 1;

    float acc[2][8][4];
#pragma unroll
    for (int i = 0; i < 2; i++)
#pragma unroll
        for (int j = 0; j < 8; j++)
#pragma unroll
            for (int l = 0; l < 4; l++) acc[i][j][l] = 0.f;

    load_chunk(0, 0); CP_COMMIT();
    load_chunk(1, 1); CP_COMMIT();

    for (int c = 0; c < nchk; c++) {
        const int stg = c % NSTG;
        CP_WAIT1();
        __syncthreads();

        const u32 stb = sbase + stg * STG_B;
#pragma unroll
        for (int ks = 0; ks < 4; ks++) {
            const int cc = ks * 2 + cq;      // chunk index 0..7
            u32 ahf[2][4], bhf[4][4], blf[4][4];
#pragma unroll
            for (int mt = 0; mt < 2; mt++)
                ldsm4(ahf[mt], stb + swz_off(rowA0 + mt * 16, cc));
#pragma unroll
            for (int ntp = 0; ntp < 4; ntp++) {
                u32 off = swz_off(rowB0 + ntp * 16, cc);
                ldsm4(bhf[ntp], stb + TILE_B + off);
                ldsm4(blf[ntp], stb + 2 * TILE_B + off);
            }
            // pass 1: Ah * Bh
#pragma unroll
            for (int mt = 0; mt < 2; mt++)
#pragma unroll
                for (int ntp = 0; ntp < 4; ntp++) {
                    mma16816h(acc[mt][ntp * 2],     ahf[mt], bhf[ntp][0], bhf[ntp][2]);
                    mma16816h(acc[mt][ntp * 2 + 1], ahf[mt], bhf[ntp][1], bhf[ntp][3]);
                }
            // pass 2: Ah * Bl
#pragma unroll
            for (int mt = 0; mt < 2; mt++)
#pragma unroll
                for (int ntp = 0; ntp < 4; ntp++) {
                    mma16816h(acc[mt][ntp * 2],     ahf[mt], blf[ntp][0], blf[ntp][2]);
                    mma16816h(acc[mt][ntp * 2 + 1], ahf[mt], blf[ntp][1], blf[ntp][3]);
                }
        }

        if (c + 2 < nchk) load_chunk(c + 2, (c + 2) % NSTG);
        CP_COMMIT();
    }

    const int g = lane >> 2;
    const int tg = lane & 3;
#pragma unroll
    for (int mt = 0; mt < 2; mt++) {
        int mrow = m0 + warp_m * 32 + mt * 16 + g;
#pragma unroll
        for (int nt = 0; nt < 8; nt++) {
            int ncol = n0 + warp_n * 64 + nt * 8 + tg * 2;
            *(float2*)(C + (size_t)mrow * ldc + ncol) =
                make_float2(acc[mt][nt][0], acc[mt][nt][1]);
            *(float2*)(C + (size_t)(mrow + 8) * ldc + ncol) =
                make_float2(acc[mt][nt][2], acc[mt][nt][3]);
        }
    }
}

__global__ __launch_bounds__(256, 1) void tgemm_nt(
    const __half* __restrict__ Ah,
    const __half* __restrict__ Bh, const __half* __restrict__ Bl,
    float* __restrict__ C, int K, int ldc)
{
    extern __shared__ __align__(1024) char ts[];
    tgemm_body(Ah, Bh, Bl, C, K, ldc, blockIdx.x * 128, blockIdx.y * 128, ts);
}

__global__ __launch_bounds__(256, 1) void tgemm4_nt(
    const __half* __restrict__ Ah,
    const __half* __restrict__ Wh, const __half* __restrict__ Wl,
    TG4Out outs, int K, int ldc)
{
    extern __shared__ __align__(1024) char ts[];
    const int wsel = blockIdx.y >> 3;
    const int n0 = (blockIdx.y & 7) * 128;
    const size_t CC = (size_t)Cq * Cq;
    float* C = (wsel == 0) ? outs.o0 : (wsel == 1) ? outs.o1
             : (wsel == 2) ? outs.o2 : outs.o3;
    tgemm_body(Ah, Wh + wsel * CC, Wl + wsel * CC, C, K, ldc,
               blockIdx.x * 128, n0, ts);
}

// ---------------- RoPE (YaRN) cos/sin table ----------------------------------
__global__ void rope_table_kernel(float* __restrict__ ct, float* __restrict__ st) {
    int idx = blockIdx.x * blockDim.x + threadIdx.x;
    if (idx >= Tq * 32) return;
    int t = idx >> 5;
    int i = idx & 31;
    double ar = (double)i / 32.0;
    double scaled_base = 10000.0 * pow(32.0, 64.0 / 62.0);
    double inv_freq = pow(scaled_base, -ar);
    double wavelen = 2.0 * M_PI * pow(10000.0, ar);
    double mscale = (wavelen - 1.0) / 31.0;
    mscale = mscale < 0.0 ? 0.0 : (mscale > 1.0 ? 1.0 : mscale);
    double scale = 1.0 + 31.0 * mscale;
    float fr = (float)(((double)t / scale) * inv_freq);
    ct[idx] = cosf(fr);
    st[idx] = sinf(fr);
}

// ---------------- beta / alpha -----------------------------------------------
#define BGM 8
__global__ __launch_bounds__(256) void bg_kernel(
    const float* __restrict__ x,
    const float* __restrict__ Wb, const float* __restrict__ bb,
    const float* __restrict__ Wgk, const float* __restrict__ bgk,
    const float* __restrict__ A_log, const float* __restrict__ dt_bias,
    float* __restrict__ beT, float* __restrict__ alT)
{
    __shared__ __align__(16) float xs[BGM][Cq];
    const int m0 = blockIdx.x * BGM;
    const int tid = threadIdx.x;
    for (int i = tid; i < BGM * Cq / 4; i += 256) {
        int r = i / (Cq / 4), cc = i % (Cq / 4);
        ((float4*)xs[r])[cc] = ((const float4*)(x + (size_t)(m0 + r) * Cq))[cc];
    }
    __syncthreads();

    const int warp = tid >> 5, lane = tid & 31;
#pragma unroll
    for (int nn = 0; nn < 4; nn++) {
        int n = warp * 4 + nn;
        const float* wr = (n < 16) ? (Wb + (size_t)n * Cq) : (Wgk + (size_t)(n - 16) * Cq);
        float wv[32];
#pragma unroll
        for (int j = 0; j < 32; j++) wv[j] = __ldg(wr + j * 32 + lane);
#pragma unroll
        for (int r = 0; r < BGM; r++) {
            float acc = 0.f;
#pragma unroll
            for (int j = 0; j < 32; j++) acc = fmaf(xs[r][j * 32 + lane], wv[j], acc);
#pragma unroll
            for (int s = 16; s > 0; s >>= 1) acc += __shfl_xor_sync(0xffffffffu, acc, s);
            if (lane == 0) {
                int m = m0 + r;
                int b = m >> 11, t = m & 2047;
                if (n < 16) {
                    beT[((size_t)b * Hq + n) * Tq + t] = 1.f / (1.f + expf(-(acc + bb[n])));
                } else {
                    int hh = n - 16;
                    float gv = acc + bgk[hh] + dt_bias[hh];
                    float sp = (gv > 20.f) ? gv : log1pf(expf(gv));
                    alT[((size_t)b * Hq + hh) * Tq + t] = expf(-expf(A_log[hh]) * sp);
                }
            }
        }
    }
}

// ---------------- conv(K=4)+silu, RoPE + l2norm (4 t per block) --------------
__global__ __launch_bounds__(256) void conv_rope_kernel(
    const float* __restrict__ qpre, const float* __restrict__ kpre,
    const float* __restrict__ vpre,
    const float* __restrict__ cqw, const float* __restrict__ cqb,
    const float* __restrict__ ckw, const float* __restrict__ ckb,
    const float* __restrict__ cvw, const float* __restrict__ cvb,
    const float* __restrict__ ct, const float* __restrict__ st,
    float* __restrict__ qo, float* __restrict__ ko, float* __restrict__ vo)
{
    // block: (b, h, 4 consecutive t)
    const int blk = blockIdx.x;
    const int b = blk / (Hq * (Tq / 4));
    const int rem = blk % (Hq * (Tq / 4));
    const int h = rem / (Tq / 4);
    const int t0 = (rem % (Tq / 4)) * 4;
    const int tid = threadIdx.x;

    __shared__ __align__(16) float spre[3][7][64];
    __shared__ float sq[4][64], sk[4][64];
    __shared__ float redq[4][2], redk[4][2];

    // load rows t0-3 .. t0+3 for the 3 tensors
    {
        const int NF4 = 3 * 7 * 16;    // float4 count
        for (int i = tid; i < NF4; i += 256) {
            int ten = i / 112;
            int r = (i % 112) / 16;
            int c4 = i % 16;
            int trow = t0 - 3 + r;
            float4 v = make_float4(0.f, 0.f, 0.f, 0.f);
            if (trow >= 0) {
                const float* src = (ten == 0) ? qpre : (ten == 1) ? kpre : vpre;
                v = ((const float4*)(src + ((size_t)b * Tq + trow) * Cq + h * 64))[c4];
            }
            ((float4*)&spre[ten][r][0])[c4] = v;
        }
    }
    __syncthreads();

    const int g = tid >> 6;          // 0..3  (t = t0+g)
    const int d = tid & 63;
    const int t = t0 + g;
    const int c = h * Dq + d;
    const size_t gidx = ((size_t)b * Tq + t) * Cq + c;

    float aq = __ldg(cqb + c), ak = __ldg(ckb + c), av = __ldg(cvb + c);
#pragma unroll
    for (int i = 0; i < 4; i++) {
        float wq = __ldg(cqw + c * 4 + i);
        float wk = __ldg(ckw + c * 4 + i);
        float wv = __ldg(cvw + c * 4 + i);
        aq = fmaf(spre[0][g + i][d], wq, aq);
        ak = fmaf(spre[1][g + i][d], wk, ak);
        av = fmaf(spre[2][g + i][d], wv, av);
    }
    vo[gidx] = av / (1.f + expf(-av));
    sq[g][d] = aq / (1.f + expf(-aq));
    sk[g][d] = ak / (1.f + expf(-ak));
    __syncthreads();

    int j = d & 31;
    int ci = (2 * j) & 31;
    float ce = ct[(size_t)t * 32 + ci];
    float se = st[(size_t)t * 32 + ci];
    float q1 = sq[g][2 * j], q2 = sq[g][2 * j + 1];
    float k1 = sk[g][2 * j], k2 = sk[g][2 * j + 1];
    float rq = (d < 32) ? (q1 * ce - q2 * se) : (q1 * se + q2 * ce);
    float rk = (d < 32) ? (k1 * ce - k2 * se) : (k1 * se + k2 * ce);

    float sq2 = rq * rq, sk2 = rk * rk;
#pragma unroll
    for (int s = 16; s > 0; s >>= 1) {
        sq2 += __shfl_xor_sync(0xffffffffu, sq2, s);
        sk2 += __shfl_xor_sync(0xffffffffu, sk2, s);
    }
    int hw = (tid >> 5) & 1;
    if ((tid & 31) == 0) { redq[g][hw] = sq2; redk[g][hw] = sk2; }
    __syncthreads();
    float qn = redq[g][0] + redq[g][1];
    float kn = redk[g][0] + redk[g][1];
    float qinv = 1.f / fmaxf(sqrtf(qn), 1e-12f);
    float kinv = 1.f / fmaxf(sqrtf(kn), 1e-12f);
    qo[gidx] = rq * qinv;
    ko[gidx] = rk * kinv;
}

// ---------------- gated-delta scan (warp per (b,h,vseg)) ---------------------
__global__ __launch_bounds__(32, 8) void scan_kernel(
    const float* __restrict__ q, const float* __restrict__ k,
    const float* __restrict__ v,
    const float* __restrict__ alT, const float* __restrict__ beT,
    const float* __restrict__ Dp, float* __restrict__ valout)
{
    const int blk = blockIdx.x;
    const int bh = blk >> 3;
    const int seg = blk & 7;
    const int b = bh >> 4;
    const int h = bh & 15;
    const int lane = threadIdx.x;
    const int vr = lane >> 2;
    const int kg = lane & 3;

    __shared__ __align__(16) float sQ[2][CHUNK][64];
    __shared__ __align__(16) float sK[2][CHUNK][64];
    __shared__ __align__(16) float sV[2][CHUNK][VSEG];
    __shared__ __align__(16) float sA[2][CHUNK];
    __shared__ __align__(16) float sB[2][CHUNK];

    const size_t base  = (size_t)b * Tq * Cq + h * Dq;
    const size_t vbase = base + seg * VSEG;
    const size_t abb   = (size_t)bh * Tq;

    auto load_chunk = [&](int c, int stg) {
        const size_t rowoff = (size_t)c * CHUNK * Cq;
#pragma unroll
        for (int it = 0; it < 8; it++) {
            int idx = it * 32 + lane;
            int row = idx >> 4;
            int col = (idx & 15) * 4;
            cpa16(&sQ[stg][row][col], q + base + rowoff + (size_t)row * Cq + col);
            cpa16(&sK[stg][row][col], k + base + rowoff + (size_t)row * Cq + col);
        }
        {
            int row = lane >> 1;
            int col = (lane & 1) * 4;
            cpa16(&sV[stg][row][col], v + vbase + rowoff + (size_t)row * Cq + col);
        }
        if (lane < 4)      cpa16(&sA[stg][lane * 4], alT + abb + c * CHUNK + lane * 4);
        else if (lane < 8) cpa16(&sB[stg][(lane - 4) * 4], beT + abb + c * CHUNK + (lane - 4) * 4);
    };

    ull S2[8];
#pragma unroll
    for (int j = 0; j < 8; j++) S2[j] = 0ULL;
    const float dp = Dp[h];

    load_chunk(0, 0); CP_COMMIT();
    load_chunk(1, 1); CP_COMMIT();
    CP_WAIT1();
    __syncwarp();

    for (int c = 0; c < NCH; c++) {
        const int stg = c & 1;
#pragma unroll 2
        for (int s = 0; s < CHUNK; s++) {
            const float a  = sA[stg][s];
            const float bt = sB[stg][s];
            const float vv = sV[stg][s][vr];

            ull k2[8], q2[8];
            const ull* kp = (const ull*)&sK[stg][s][kg * 16];
            const ull* qp = (const ull*)&sQ[stg][s][kg * 16];
#pragma unroll
            for (int j = 0; j < 8; j++) { k2[j] = kp[j]; q2[j] = qp[j]; }

            ull pA = 0ULL, pB = 0ULL;
#pragma unroll
            for (int j = 0; j < 4; j++) {
                pA = ffma2(S2[j], k2[j], pA);
                pB = ffma2(S2[j + 4], k2[j + 4], pB);
            }
            float2 pu = unpack2(fadd2(pA, pB));
            float p = pu.x + pu.y;
            p += __shfl_xor_sync(0xffffffffu, p, 1);
            p += __shfl_xor_sync(0xffffffffu, p, 2);

            const float coef = bt * vv - a * bt * p;
            const ull c2 = pack2(coef, coef);
            const ull a2 = pack2(a, a);

            ull oA = 0ULL, oB = 0ULL;
#pragma unroll
            for (int j = 0; j < 4; j++) {
                S2[j] = ffma2(a2, S2[j], fmul2(c2, k2[j]));
                oA = ffma2(S2[j], q2[j], oA);
                S2[j + 4] = ffma2(a2, S2[j + 4], fmul2(c2, k2[j + 4]));
                oB = ffma2(S2[j + 4], q2[j + 4], oB);
            }
            float2 ou = unpack2(fadd2(oA, oB));
            float o = ou.x + ou.y;
            o += __shfl_xor_sync(0xffffffffu, o, 1);
            o += __shfl_xor_sync(0xffffffffu, o, 2);

            if (kg == 0) {
                float val = fmaf(dp, vv, o);
                valout[vbase + (size_t)(c * CHUNK + s) * Cq + vr] = val;
            }
        }
        if (c + 2 < NCH) load_chunk(c + 2, stg);
        CP_COMMIT();
        CP_WAIT1();
        __syncwarp();
    }
}

// ---------------- epilogue: rmsnorm -> silu -> *gate -> fp16 -----------------
__global__ __launch_bounds__(256) void epi_kernel(
    const float* __restrict__ val, const float* __restrict__ gate,
    const float* __restrict__ onw, __half* __restrict__ ogh)
{
    const int gw = blockIdx.x * 8 + (threadIdx.x >> 5);
    const int lane = threadIdx.x & 31;
    const size_t off = (size_t)gw * 64 + lane * 2;
    float2 vl = *(const float2*)(val + off);
    float ss = vl.x * vl.x + vl.y * vl.y;
#pragma unroll
    for (int s = 16; s > 0; s >>= 1) ss += __shfl_xor_sync(0xffffffffu, ss, s);
    float r = rsqrtf(ss * (1.f / 64.f) + EPSq);
    float2 w2 = *(const float2*)(onw + lane * 2);
    float2 g2 = *(const float2*)(gate + off);
    float y0 = vl.x * r * w2.x;
    float y1 = vl.y * r * w2.y;
    float o0 = g2.x * (y0 / (1.f + expf(-y0)));
    float o1 = g2.y * (y1 / (1.f + expf(-y1)));
    *(u32*)(ogh + off) = packh(__float2half(o0), __float2half(o1));
}

// ---------------- launch ------------------------------------------------------
extern "C" void kernel_launch(void* const* d_in, const int* in_sizes, int n_in,
                              void* d_out, int out_size)
{
    const float* x    = (const float*)d_in[0];
    const float* Wq   = (const float*)d_in[1];
    const float* Wk   = (const float*)d_in[2];
    const float* Wv   = (const float*)d_in[3];
    const float* Wg   = (const float*)d_in[4];
    const float* Wo   = (const float*)d_in[5];
    const float* Wb   = (const float*)d_in[6];
    const float* bb   = (const float*)d_in[7];
    const float* Wgk  = (const float*)d_in[8];
    const float* bgk  = (const float*)d_in[9];
    const float* cqw  = (const float*)d_in[10];
    const float* cqb  = (const float*)d_in[11];
    const float* ckw  = (const float*)d_in[12];
    const float* ckb  = (const float*)d_in[13];
    const float* cvw  = (const float*)d_in[14];
    const float* cvb  = (const float*)d_in[15];
    const float* A_log = (const float*)d_in[16];
    const float* Dp   = (const float*)d_in[17];
    const float* dtb  = (const float*)d_in[18];
    const float* onw  = (const float*)d_in[19];
    float* out = (float*)d_out;

    float *qpre, *kpre, *vpre, *gbuf, *qn, *kn, *vn, *al, *be, *ct, *st;
    __half *xh, *wh, *wl, *ogh;
    cudaGetSymbolAddress((void**)&qpre, g_qpre);
    cudaGetSymbolAddress((void**)&kpre, g_kpre);
    cudaGetSymbolAddress((void**)&vpre, g_vpre);
    cudaGetSymbolAddress((void**)&gbuf, g_gate);
    cudaGetSymbolAddress((void**)&qn,   g_q);
    cudaGetSymbolAddress((void**)&kn,   g_k);
    cudaGetSymbolAddress((void**)&vn,   g_v);
    cudaGetSymbolAddress((void**)&al,   g_alT);
    cudaGetSymbolAddress((void**)&be,   g_beT);
    cudaGetSymbolAddress((void**)&ct,   g_cos);
    cudaGetSymbolAddress((void**)&st,   g_sin);
    cudaGetSymbolAddress((void**)&xh,   g_xh);
    cudaGetSymbolAddress((void**)&wh,   g_wh);
    cudaGetSymbolAddress((void**)&wl,   g_wl);
    cudaGetSymbolAddress((void**)&ogh,  g_ogh);

    cudaFuncSetAttribute(tgemm_nt,  cudaFuncAttributeMaxDynamicSharedMemorySize, TG_SMEM);
    cudaFuncSetAttribute(tgemm4_nt, cudaFuncAttributeMaxDynamicSharedMemorySize, TG_SMEM);

    rope_table_kernel<<<(Tq * 32 + 255) / 256, 256>>>(ct, st);

    const size_t CC = (size_t)Cq * Cq;
    const int R4 = (int)(CC / 4);
    split_h_kernel<<<(Mq * Cq / 4 + 255) / 256, 256>>>(x, xh, Mq * Cq / 4);
    wsplit_kernel<<<(5 * R4 + 255) / 256, 256>>>(Wq, Wk, Wv, Wg, Wo, wh, wl);

    bg_kernel<<<Mq / BGM, 256>>>(x, Wb, bb, Wgk, bgk, A_log, dtb, be, al);

    TG4Out outs = {qpre, kpre, vpre, gbuf};
    dim3 g4(Mq / 128, 32);
    tgemm4_nt<<<g4, 256, TG_SMEM>>>(xh, wh, wl, outs, Cq, Cq);

    conv_rope_kernel<<<Bq * Hq * (Tq / 4), 256>>>(qpre, kpre, vpre,
                                                  cqw, cqb, ckw, ckb, cvw, cvb,
                                                  ct, st, qn, kn, vn);

    scan_kernel<<<Bq * Hq * NSEG, 32>>>(qn, kn, vn, al, be, Dp, qpre);

    epi_kernel<<<(Bq * Tq * Hq) / 8, 256>>>(qpre, gbuf, onw, ogh);

    dim3 gg(Mq / 128, Cq / 128);
    tgemm_nt<<<gg, 256, TG_SMEM>>>(ogh, wh + 4 * CC, wl + 4 * CC, out, Cq, Cq);
}